// round 2
// baseline (speedup 1.0000x reference)
#include <cuda_runtime.h>
#include <cuda_fp16.h>
#include <mma.h>

using namespace nvcuda;

#define HIDDEN   192
#define IN2      384          // 2*HIDDEN
#define NNODES   262144
#define NEDGES   262144
#define NSEG     16384
#define DEG      16

// ---------------- scratch (static device globals; no allocs allowed) --------
__device__ __half g_X[(size_t)NNODES * HIDDEN];      // node embeddings, fp16
__device__ __half g_W1h[IN2 * IN2];
__device__ __half g_W2h[IN2 * HIDDEN];
__device__ __half g_W3h[HIDDEN * HIDDEN];

// ---------------- kernel 1: sincos embedding --------------------------------
// emb layout per node: for d in 0..2: [sin(p_d*w_0..31) | cos(p_d*w_0..31)]
__global__ void embed_kernel(const float* __restrict__ pos) {
    int idx = blockIdx.x * blockDim.x + threadIdx.x;
    if (idx >= NNODES * HIDDEN) return;
    int n = idx / HIDDEN;
    int c = idx - n * HIDDEN;
    int d = c >> 6;            // c / 64
    int r = c & 63;
    int j = r & 31;
    // omega_j = 10000^(-j/32) = exp2(-j * log2(10000)/32)
    float omega = exp2f(-(float)j * (13.287712379549449f / 32.0f));
    float v = pos[n * 3 + d] * omega;
    float s = (r < 32) ? sinf(v) : cosf(v);
    g_X[idx] = __float2half(s);
}

// ---------------- kernel 2: weight convert fp32 -> fp16 ---------------------
__global__ void wconv_kernel(const float* __restrict__ W1,
                             const float* __restrict__ W2,
                             const float* __restrict__ W3) {
    int i = blockIdx.x * blockDim.x + threadIdx.x;
    if (i < IN2 * IN2)    g_W1h[i] = __float2half(W1[i]);
    if (i < IN2 * HIDDEN) g_W2h[i] = __float2half(W2[i]);
    if (i < HIDDEN * HIDDEN) g_W3h[i] = __float2half(W3[i]);
}

// ---------------- kernel 3: fused edge MLP + segment mean -------------------
// Per CTA: 128 edge rows = 8 segments of 16 contiguous edges.
// SMEM plan (bytes):
//   [0      .. 100352)  sH0: half[128][392]  (layer1 input; later sH2 half[128][200])
//   [100352 .. 200704)  sH1: half[128][392]  (layer1 out;  later sY float[128][196])
//   [200704 .. 214016)  sW : half[64][104]   (weight K-slice staging)
//   [214016 .. 224256)  sScr: per-warp float[16][20] epilogue staging (8 warps)
//   [224256 .. 225280)  sIdx: int[128*2] edge indices
#define SMEM_BYTES 225280
#define H0S 392
#define H2S 200
#define YS  196
#define WS  104

__device__ __forceinline__ float gelu_exact(float x) {
    return 0.5f * x * (1.0f + erff(x * 0.70710678118654752f));
}

template<int KDIM, int NDIMW, bool GELU, bool TOHALF>
__device__ __forceinline__ void layer_gemm(
    const __half* __restrict__ inBuf, int inStride,
    const __half* __restrict__ Wg, const float* __restrict__ bias,
    __half* __restrict__ outH, int outStride,
    float* __restrict__ outF, int outFStride,
    __half* __restrict__ sW, float* __restrict__ sScr, int tid)
{
    const int warp  = tid >> 5;
    const int lane  = tid & 31;
    const int warpM = warp & 3;   // 4 warps over M (32 rows each)
    const int warpN = warp >> 2;  // 2 warps over N (48 cols each within 96 chunk)
    float* scr = sScr + warp * 16 * 20;

    const int NCH = NDIMW / 96;
    const int KCH = KDIM / 64;

    for (int nc = 0; nc < NCH; nc++) {
        const int n0 = nc * 96;
        wmma::fragment<wmma::accumulator, 16, 16, 16, float> acc[2][3];
        #pragma unroll
        for (int i = 0; i < 2; i++)
            #pragma unroll
            for (int j = 0; j < 3; j++)
                wmma::fill_fragment(acc[i][j], 0.0f);

        for (int kc = 0; kc < KCH; kc++) {
            const int k0 = kc * 64;
            __syncthreads();   // sW safe to overwrite
            // stage W[k0:k0+64, n0:n0+96) -> sW[64][104]; 12 uint4 per row
            #pragma unroll 1
            for (int i = tid; i < 64 * 12; i += 256) {
                int kk = i / 12, q = i - kk * 12;
                *((uint4*)(sW + kk * WS) + q) =
                    *((const uint4*)(Wg + (size_t)(k0 + kk) * NDIMW + n0) + q);
            }
            __syncthreads();
            #pragma unroll
            for (int k16 = 0; k16 < 4; k16++) {
                wmma::fragment<wmma::matrix_a, 16, 16, 16, __half, wmma::row_major> a[2];
                #pragma unroll
                for (int i = 0; i < 2; i++)
                    wmma::load_matrix_sync(a[i],
                        inBuf + (warpM * 32 + i * 16) * inStride + k0 + k16 * 16,
                        inStride);
                #pragma unroll
                for (int j = 0; j < 3; j++) {
                    wmma::fragment<wmma::matrix_b, 16, 16, 16, __half, wmma::row_major> b;
                    wmma::load_matrix_sync(b, sW + (k16 * 16) * WS + warpN * 48 + j * 16, WS);
                    #pragma unroll
                    for (int i = 0; i < 2; i++)
                        wmma::mma_sync(acc[i][j], a[i], b, acc[i][j]);
                }
            }
        }
        // epilogue: per-warp fragment staging -> bias -> (gelu) -> write
        #pragma unroll
        for (int i = 0; i < 2; i++) {
            #pragma unroll
            for (int j = 0; j < 3; j++) {
                wmma::store_matrix_sync(scr, acc[i][j], 20, wmma::mem_row_major);
                __syncwarp();
                const int rowB = warpM * 32 + i * 16;
                const int colB = n0 + warpN * 48 + j * 16;
                #pragma unroll
                for (int t = lane; t < 256; t += 32) {
                    int r = t >> 4, c = t & 15;
                    float v = scr[r * 20 + c] + bias[colB + c];
                    if (GELU) v = gelu_exact(v);
                    if (TOHALF)
                        outH[(rowB + r) * outStride + colB + c] = __float2half(v);
                    else
                        outF[(rowB + r) * outFStride + colB + c] = v;
                }
                __syncwarp();
            }
        }
    }
    __syncthreads();
}

__global__ __launch_bounds__(256, 1)
void mlp_kernel(const int* __restrict__ edges,
                const float* __restrict__ b1,
                const float* __restrict__ b2,
                const float* __restrict__ b3,
                float* __restrict__ out)
{
    extern __shared__ char smem[];
    __half* sH0  = (__half*)(smem);
    __half* sH1  = (__half*)(smem + 100352);
    __half* sH2  = (__half*)(smem);            // reuses sH0 region
    float*  sY   = (float*)(smem + 100352);    // reuses sH1 region
    __half* sW   = (__half*)(smem + 200704);
    float*  sScr = (float*)(smem + 214016);
    int*    sIdx = (int*)(smem + 224256);

    const int tid = threadIdx.x;
    const int e0  = blockIdx.x * 128;

    // edge indices for this tile: [dst, src] pairs
    for (int i = tid; i < 256; i += 256) sIdx[i] = edges[e0 * 2 + i];
    __syncthreads();

    // gather: row = [ x[src] (192) | x[dst] (192) ], 48 uint4 per row
    #pragma unroll 1
    for (int i = tid; i < 128 * 48; i += 256) {
        int row = i / 48, q = i - row * 48;
        int isDst = (q >= 24);
        int node  = sIdx[row * 2 + (isDst ? 0 : 1)];
        int qq    = isDst ? (q - 24) : q;
        uint4 v = *((const uint4*)(g_X + (size_t)node * HIDDEN) + qq);
        *((uint4*)(sH0 + row * H0S + (isDst ? HIDDEN : 0)) + qq) = v;
    }
    __syncthreads();

    // layer 1: [128,384]@[384,384] + b1, gelu  -> sH1 (fp16)
    layer_gemm<IN2, IN2, true, true>(sH0, H0S, g_W1h, b1, sH1, H0S, nullptr, 0, sW, sScr, tid);
    // layer 2: [128,384]@[384,192] + b2, gelu  -> sH2 (fp16, in sH0 region)
    layer_gemm<IN2, HIDDEN, true, true>(sH1, H0S, g_W2h, b2, sH2, H2S, nullptr, 0, sW, sScr, tid);
    // layer 3: [128,192]@[192,192] + b3        -> sY (fp32, in sH1 region)
    layer_gemm<HIDDEN, HIDDEN, false, false>(sH2, H2S, g_W3h, b3, nullptr, 0, sY, YS, sW, sScr, tid);

    // segment mean: 8 segments x 16 rows -> out[seg][192]
    const int seg0 = blockIdx.x * 8;
    #pragma unroll 1
    for (int i = tid; i < 8 * HIDDEN; i += 256) {
        int s = i / HIDDEN, c = i - s * HIDDEN;
        float acc = 0.0f;
        #pragma unroll
        for (int r = 0; r < DEG; r++) acc += sY[(s * DEG + r) * YS + c];
        out[(size_t)(seg0 + s) * HIDDEN + c] = acc * (1.0f / 16.0f);
    }
}

// ---------------- launch ----------------------------------------------------
extern "C" void kernel_launch(void* const* d_in, const int* in_sizes, int n_in,
                              void* d_out, int out_size) {
    const float* mesh_pos   = (const float*)d_in[0];
    const int*   mesh_edges = (const int*)d_in[1];
    // d_in[2] = batch_idx (unused by the reference computation)
    const float* W1 = (const float*)d_in[3];
    const float* b1 = (const float*)d_in[4];
    const float* W2 = (const float*)d_in[5];
    const float* b2 = (const float*)d_in[6];
    const float* W3 = (const float*)d_in[7];
    const float* b3 = (const float*)d_in[8];
    float* out = (float*)d_out;

    cudaFuncSetAttribute(mlp_kernel, cudaFuncAttributeMaxDynamicSharedMemorySize, SMEM_BYTES);

    embed_kernel<<<(NNODES * HIDDEN + 255) / 256, 256>>>(mesh_pos);
    wconv_kernel<<<(IN2 * IN2 + 255) / 256, 256>>>(W1, W2, W3);
    mlp_kernel<<<NEDGES / 128, 256, SMEM_BYTES>>>(mesh_edges, b1, b2, b3, out);
}

// round 7
// speedup vs baseline: 1.4346x; 1.4346x over previous
#include <cuda_runtime.h>
#include <cuda_fp16.h>
#include <cstdint>

#define HIDDEN 192
#define NNODES 262144
#define SA 392           // sA row stride in halfs (784B -> ldmatrix phase rot 1)

// ---------------- device scratch (no allocs allowed) ----------------
__device__ __half g_X[(size_t)NNODES * HIDDEN];     // node embeddings fp16
__device__ __align__(16) __half g_Wprep[258048];    // 15 chunk-contiguous weight pieces

// ---------------- helpers ----------------
__device__ __forceinline__ uint32_t smem_u32(const void* p) {
    uint32_t a;
    asm("{ .reg .u64 t; cvta.to.shared.u64 t, %1; cvt.u32.u64 %0, t; }" : "=r"(a) : "l"(p));
    return a;
}
__device__ __forceinline__ void cp16(uint32_t dst, const __half* src) {
    unsigned long long g = __cvta_generic_to_global(src);
    asm volatile("cp.async.cg.shared.global [%0], [%1], 16;" :: "r"(dst), "l"(g) : "memory");
}
#define CP_COMMIT() asm volatile("cp.async.commit_group;" ::: "memory")
#define CP_WAIT1()  asm volatile("cp.async.wait_group 1;" ::: "memory")

__device__ __forceinline__ void ldsm4(uint32_t* r, uint32_t addr) {
    asm volatile("ldmatrix.sync.aligned.m8n8.x4.shared.b16 {%0,%1,%2,%3}, [%4];"
        : "=r"(r[0]), "=r"(r[1]), "=r"(r[2]), "=r"(r[3]) : "r"(addr));
}
__device__ __forceinline__ void ldsm4t(uint32_t* r, uint32_t addr) {
    asm volatile("ldmatrix.sync.aligned.m8n8.x4.trans.shared.b16 {%0,%1,%2,%3}, [%4];"
        : "=r"(r[0]), "=r"(r[1]), "=r"(r[2]), "=r"(r[3]) : "r"(addr));
}
__device__ __forceinline__ void mma16816(float* d, const uint32_t* a, uint32_t b0, uint32_t b1) {
    asm volatile("mma.sync.aligned.m16n8k16.row.col.f32.f16.f16.f32 "
        "{%0,%1,%2,%3}, {%4,%5,%6,%7}, {%8,%9}, {%0,%1,%2,%3};"
        : "+f"(d[0]), "+f"(d[1]), "+f"(d[2]), "+f"(d[3])
        : "r"(a[0]), "r"(a[1]), "r"(a[2]), "r"(a[3]), "r"(b0), "r"(b1));
}
__device__ __forceinline__ float gelu_exact(float x) {
    return 0.5f * x * (1.0f + erff(x * 0.70710678118654752f));
}
__device__ __forceinline__ uint32_t packh2(float x, float y) {
    __half2 h = __floats2half2_rn(x, y);
    return *reinterpret_cast<uint32_t*>(&h);
}

// ---------------- kernel 1: sincos embedding (MUFU) ----------------
__global__ void embed_kernel(const float* __restrict__ pos) {
    int idx = blockIdx.x * blockDim.x + threadIdx.x;
    if (idx >= NNODES * 96) return;
    int n = idx / 96;
    int t = idx - n * 96;
    int d = t >> 5, j = t & 31;
    float omega = exp2f(-(float)j * (13.287712379549449f / 32.0f));
    float v = pos[n * 3 + d] * omega;
    float s, c;
    __sincosf(v, &s, &c);
    __half* xp = g_X + (size_t)n * HIDDEN + d * 64;
    xp[j]      = __float2half(s);
    xp[32 + j] = __float2half(c);
}

// ---------------- kernel 2: weight prep (transpose into chunk layout) -------
// chunks (half elem offsets):
//  L1 nc=0..5 : base nc*24576,            elem k*64+n   <- W1[k][nc*64+n]   (384k x 64n)
//  L2 kc=0..5 : base 147456 + kc*12288,   elem k*192+n  <- W2[kc*64+k][n]   (64k x 192n)
//  L3 kc=0..2 : base 221184 + kc*12288,   elem k*192+n  <- W3[kc*64+k][n]
__global__ void wprep_kernel(const float* __restrict__ W1,
                             const float* __restrict__ W2,
                             const float* __restrict__ W3) {
    int e = blockIdx.x * blockDim.x + threadIdx.x;
    if (e >= 258048) return;
    float w;
    if (e < 147456) {
        int nc = e / 24576, r = e - nc * 24576;
        int k = r >> 6, n = r & 63;
        w = W1[k * 384 + nc * 64 + n];
    } else if (e < 221184) {
        int f = e - 147456;
        int kc = f / 12288, r = f - kc * 12288;
        int k = r / 192, n = r - k * 192;
        w = W2[(kc * 64 + k) * 192 + n];
    } else {
        int f = e - 221184;
        int kc = f / 12288, r = f - kc * 12288;
        int k = r / 192, n = r - k * 192;
        w = W3[(kc * 64 + k) * 192 + n];
    }
    g_Wprep[e] = __float2half(w);
}

// ---------------- kernel 3: fused register-chained MLP + segment mean -------
// SMEM (bytes):
//   0      : sA    128 x 392 halfs (100352)    gathered h0
//   100352 : sB    2 x 55296 weight ring       (L1 chunk: [384][72]h; L2/L3: [64][200]h)
//   210944 : sOut  float[8][192] (6144)
//   217088 : sBias float[768]    (3072)        b1|b2|b3
//   220160 : sIdx  int[256]      (1024)
#define SMEM_BYTES 221184
#define SB_OFF 100352
#define BUFSZ  55296

__device__ __forceinline__ void issue_chunk(int id, uint32_t sB, int tid) {
    uint32_t dst = sB + (uint32_t)(id & 1) * BUFSZ;
    if (id < 6) {
        const __half* src = g_Wprep + (size_t)id * 24576;
        #pragma unroll
        for (int i = 0; i < 12; i++) {
            int idx = tid + i * 256;
            int row = idx >> 3, q = idx & 7;
            cp16(dst + row * 144 + q * 16, src + idx * 8);
        }
    } else if (id < 15) {
        const __half* src = g_Wprep + 147456 + (size_t)(id - 6) * 12288;
        #pragma unroll
        for (int i = 0; i < 6; i++) {
            int idx = tid + i * 256;
            int row = idx / 24, q = idx - row * 24;
            cp16(dst + row * 400 + q * 16, src + idx * 8);
        }
    }
}

__global__ __launch_bounds__(256, 1)
void mlp_kernel(const int* __restrict__ edges,
                const float* __restrict__ b1,
                const float* __restrict__ b2,
                const float* __restrict__ b3,
                float* __restrict__ out)
{
    extern __shared__ char smem[];
    const uint32_t base = smem_u32(smem);
    const uint32_t sA = base;
    const uint32_t sB = base + SB_OFF;
    float* sOut  = (float*)(smem + 210944);
    float* sBias = (float*)(smem + 217088);
    int*   sIdx  = (int*)(smem + 220160);

    const int tid  = threadIdx.x;
    const int wid  = tid >> 5;
    const int lane = tid & 31;

    // start weight pipeline immediately
    issue_chunk(0, sB, tid); CP_COMMIT();
    issue_chunk(1, sB, tid); CP_COMMIT();

    // biases + edge indices
    for (int i = tid; i < 384; i += 256) sBias[i] = b1[i];
    if (tid < 192) { sBias[384 + tid] = b2[tid]; sBias[576 + tid] = b3[tid]; }
    sIdx[tid] = edges[blockIdx.x * 256 + tid];
    __syncthreads();

    // gather h0 = [x[src] | x[dst]] rows into sA (stride 392 halfs)
    #pragma unroll 1
    for (int i = tid; i < 128 * 48; i += 256) {
        int row = i / 48;
        int q   = i - row * 48;
        int isDst = (q >= 24);
        int node  = sIdx[row * 2 + (isDst ? 0 : 1)];
        int qq    = isDst ? (q - 24) : q;
        uint4 v = *((const uint4*)(g_X + (size_t)node * HIDDEN) + qq);
        *(uint4*)(smem + row * 784 + isDst * 384 + qq * 16) = v;
    }

    // per-thread fragment addresses (A and B share the (lane&15, lane>>4) form)
    const uint32_t pA  = sA + (uint32_t)((wid * 16 + (lane & 15)) * SA + (lane >> 4) * 8) * 2;
    const uint32_t bo1 = (uint32_t)(lane & 15) * 144 + (uint32_t)(lane >> 4) * 16;  // L1 stride 72h
    const uint32_t bo2 = (uint32_t)(lane & 15) * 400 + (uint32_t)(lane >> 4) * 16;  // L2/3 stride 200h
    const int t2 = (lane & 3) * 2;

    uint32_t aH1[96];   // h1 rows (16) x K=384 as A-fragments
    // ================= layer 1 (+ keep h1 in regs) =================
    #pragma unroll
    for (int c = 0; c < 6; c++) {
        CP_WAIT1();
        __syncthreads();
        float acc[8][4];
        #pragma unroll
        for (int j = 0; j < 8; j++)
            #pragma unroll
            for (int r = 0; r < 4; r++) acc[j][r] = 0.0f;

        const uint32_t bufB = sB + (uint32_t)(c & 1) * BUFSZ + bo1;
        #pragma unroll 4
        for (int kc = 0; kc < 24; kc++) {
            uint32_t a[4];
            ldsm4(a, pA + kc * 32);
            #pragma unroll
            for (int nt = 0; nt < 4; nt++) {
                uint32_t b[4];
                ldsm4t(b, bufB + kc * 2304 + nt * 32);
                mma16816(acc[2 * nt],     a, b[0], b[1]);
                mma16816(acc[2 * nt + 1], a, b[2], b[3]);
            }
        }
        __syncthreads();
        issue_chunk(c + 2, sB, tid); CP_COMMIT();

        // epilogue: bias + exact gelu -> A-fragments for layer 2
        #pragma unroll
        for (int kl = 0; kl < 4; kl++) {
            int j0 = 2 * kl, j1 = 2 * kl + 1;
            float2 bA = *(float2*)&sBias[c * 64 + j0 * 8 + t2];
            float2 bB = *(float2*)&sBias[c * 64 + j1 * 8 + t2];
            int ix = c * 16 + kl * 4;
            aH1[ix + 0] = packh2(gelu_exact(acc[j0][0] + bA.x), gelu_exact(acc[j0][1] + bA.y));
            aH1[ix + 1] = packh2(gelu_exact(acc[j0][2] + bA.x), gelu_exact(acc[j0][3] + bA.y));
            aH1[ix + 2] = packh2(gelu_exact(acc[j1][0] + bB.x), gelu_exact(acc[j1][1] + bB.y));
            aH1[ix + 3] = packh2(gelu_exact(acc[j1][2] + bB.x), gelu_exact(acc[j1][3] + bB.y));
        }
    }

    // ================= layer 2 =================
    float acc2[24][4];
    #pragma unroll
    for (int j = 0; j < 24; j++)
        #pragma unroll
        for (int r = 0; r < 4; r++) acc2[j][r] = 0.0f;

    #pragma unroll
    for (int cc = 0; cc < 6; cc++) {
        CP_WAIT1();
        __syncthreads();
        const uint32_t bufB = sB + (uint32_t)((6 + cc) & 1) * BUFSZ + bo2;
        #pragma unroll
        for (int kl = 0; kl < 4; kl++) {
            const uint32_t* a = &aH1[(4 * cc + kl) * 4];
            #pragma unroll
            for (int nt = 0; nt < 12; nt++) {
                uint32_t b[4];
                ldsm4t(b, bufB + kl * 6400 + nt * 32);
                mma16816(acc2[2 * nt],     a, b[0], b[1]);
                mma16816(acc2[2 * nt + 1], a, b[2], b[3]);
            }
        }
        __syncthreads();
        issue_chunk(8 + cc, sB, tid); CP_COMMIT();
    }

    // epilogue: bias + gelu -> A-fragments for layer 3
    uint32_t aH2[48];
    #pragma unroll
    for (int kl = 0; kl < 12; kl++) {
        int j0 = 2 * kl, j1 = 2 * kl + 1;
        float2 bA = *(float2*)&sBias[384 + j0 * 8 + t2];
        float2 bB = *(float2*)&sBias[384 + j1 * 8 + t2];
        aH2[kl * 4 + 0] = packh2(gelu_exact(acc2[j0][0] + bA.x), gelu_exact(acc2[j0][1] + bA.y));
        aH2[kl * 4 + 1] = packh2(gelu_exact(acc2[j0][2] + bA.x), gelu_exact(acc2[j0][3] + bA.y));
        aH2[kl * 4 + 2] = packh2(gelu_exact(acc2[j1][0] + bB.x), gelu_exact(acc2[j1][1] + bB.y));
        aH2[kl * 4 + 3] = packh2(gelu_exact(acc2[j1][2] + bB.x), gelu_exact(acc2[j1][3] + bB.y));
    }

    // ================= layer 3 =================
    float acc3[24][4];
    #pragma unroll
    for (int j = 0; j < 24; j++)
        #pragma unroll
        for (int r = 0; r < 4; r++) acc3[j][r] = 0.0f;

    #pragma unroll
    for (int cc = 0; cc < 3; cc++) {
        CP_WAIT1();
        __syncthreads();
        const uint32_t bufB = sB + (uint32_t)((12 + cc) & 1) * BUFSZ + bo2;
        #pragma unroll
        for (int kl = 0; kl < 4; kl++) {
            const uint32_t* a = &aH2[(4 * cc + kl) * 4];
            #pragma unroll
            for (int nt = 0; nt < 12; nt++) {
                uint32_t b[4];
                ldsm4t(b, bufB + kl * 6400 + nt * 32);
                mma16816(acc3[2 * nt],     a, b[0], b[1]);
                mma16816(acc3[2 * nt + 1], a, b[2], b[3]);
            }
        }
        __syncthreads();
        issue_chunk(14 + cc, sB, tid); CP_COMMIT();   // ids >= 15 are empty groups
    }

    // ===== fused segment mean: warp w == segment w (16 contiguous edges) =====
    #pragma unroll
    for (int tn = 0; tn < 24; tn++) {
        float s0 = acc3[tn][0] + acc3[tn][2];
        float s1 = acc3[tn][1] + acc3[tn][3];
        s0 += __shfl_xor_sync(0xFFFFFFFFu, s0, 4);
        s0 += __shfl_xor_sync(0xFFFFFFFFu, s0, 8);
        s0 += __shfl_xor_sync(0xFFFFFFFFu, s0, 16);
        s1 += __shfl_xor_sync(0xFFFFFFFFu, s1, 4);
        s1 += __shfl_xor_sync(0xFFFFFFFFu, s1, 8);
        s1 += __shfl_xor_sync(0xFFFFFFFFu, s1, 16);
        if (lane < 4) {
            int col = tn * 8 + lane * 2;
            float2 b = *(float2*)&sBias[576 + col];
            float2 o;
            o.x = s0 * 0.0625f + b.x;
            o.y = s1 * 0.0625f + b.y;
            *(float2*)&sOut[wid * 192 + col] = o;
        }
    }
    __syncthreads();

    // coalesced block store: 8 segments x 192 floats, contiguous
    {
        float4* o4 = (float4*)(out + (size_t)blockIdx.x * 1536);
        const float4* s4 = (const float4*)sOut;
        for (int i = tid; i < 384; i += 256) o4[i] = s4[i];
    }
}

// ---------------- launch ----------------
extern "C" void kernel_launch(void* const* d_in, const int* in_sizes, int n_in,
                              void* d_out, int out_size) {
    const float* mesh_pos   = (const float*)d_in[0];
    const int*   mesh_edges = (const int*)d_in[1];
    const float* W1 = (const float*)d_in[3];
    const float* b1 = (const float*)d_in[4];
    const float* W2 = (const float*)d_in[5];
    const float* b2 = (const float*)d_in[6];
    const float* W3 = (const float*)d_in[7];
    const float* b3 = (const float*)d_in[8];
    float* out = (float*)d_out;

    cudaFuncSetAttribute(mlp_kernel, cudaFuncAttributeMaxDynamicSharedMemorySize, SMEM_BYTES);

    embed_kernel<<<(NNODES * 96 + 255) / 256, 256>>>(mesh_pos);
    wprep_kernel<<<(258048 + 255) / 256, 256>>>(W1, W2, W3);
    mlp_kernel<<<2048, 256, SMEM_BYTES>>>(mesh_edges, b1, b2, b3, out);
}

// round 9
// speedup vs baseline: 1.6608x; 1.1577x over previous
#include <cuda_runtime.h>
#include <cuda_fp16.h>
#include <cstdint>

#define HIDDEN 192
#define NNODES 262144

// ---------------- device scratch (no allocs allowed) ----------------
__device__ __half g_X[(size_t)NNODES * HIDDEN];     // node embeddings fp16
__device__ __align__(16) __half g_Wprep[258048];    // 15 chunk-contiguous weight pieces

// ---------------- helpers ----------------
__device__ __forceinline__ uint32_t smem_u32(const void* p) {
    uint32_t a;
    asm("{ .reg .u64 t; cvta.to.shared.u64 t, %1; cvt.u32.u64 %0, t; }" : "=r"(a) : "l"(p));
    return a;
}
__device__ __forceinline__ void cp16(uint32_t dst, const __half* src) {
    unsigned long long g = __cvta_generic_to_global(src);
    asm volatile("cp.async.cg.shared.global [%0], [%1], 16;" :: "r"(dst), "l"(g) : "memory");
}
#define CP_COMMIT() asm volatile("cp.async.commit_group;" ::: "memory")
#define CP_WAIT2()  asm volatile("cp.async.wait_group 2;" ::: "memory")

__device__ __forceinline__ void ldsm4t(uint32_t* r, uint32_t addr) {
    asm volatile("ldmatrix.sync.aligned.m8n8.x4.trans.shared.b16 {%0,%1,%2,%3}, [%4];"
        : "=r"(r[0]), "=r"(r[1]), "=r"(r[2]), "=r"(r[3]) : "r"(addr));
}
__device__ __forceinline__ void mma16816(float* d, const uint32_t* a, uint32_t b0, uint32_t b1) {
    asm volatile("mma.sync.aligned.m16n8k16.row.col.f32.f16.f16.f32 "
        "{%0,%1,%2,%3}, {%4,%5,%6,%7}, {%8,%9}, {%0,%1,%2,%3};"
        : "+f"(d[0]), "+f"(d[1]), "+f"(d[2]), "+f"(d[3])
        : "r"(a[0]), "r"(a[1]), "r"(a[2]), "r"(a[3]), "r"(b0), "r"(b1));
}
__device__ __forceinline__ float gelu_exact(float x) {
    return 0.5f * x * (1.0f + erff(x * 0.70710678118654752f));
}
__device__ __forceinline__ uint32_t packh2(float x, float y) {
    __half2 h = __floats2half2_rn(x, y);
    return *reinterpret_cast<uint32_t*>(&h);
}

// ---------------- kernel 1: sincos embedding (MUFU, 8B stores) --------------
__global__ void embed_kernel(const float* __restrict__ pos) {
    int idx = blockIdx.x * blockDim.x + threadIdx.x;
    if (idx >= NNODES * 24) return;
    int n = idx / 24;
    int t = idx - n * 24;
    int d = t >> 3, q = t & 7;
    int j0 = q * 4;
    float p = pos[n * 3 + d];
    float s[4], c[4];
    #pragma unroll
    for (int i = 0; i < 4; i++) {
        float omega = exp2f(-(float)(j0 + i) * (13.287712379549449f / 32.0f));
        __sincosf(p * omega, &s[i], &c[i]);
    }
    uint2 sv, cv;
    sv.x = packh2(s[0], s[1]); sv.y = packh2(s[2], s[3]);
    cv.x = packh2(c[0], c[1]); cv.y = packh2(c[2], c[3]);
    __half* xp = g_X + (size_t)n * HIDDEN + d * 64;
    *(uint2*)(xp + j0)      = sv;
    *(uint2*)(xp + 32 + j0) = cv;
}

// ---------------- kernel 2: weight prep (transpose into chunk layout) -------
//  L1 nc=0..5 : base nc*24576,            elem k*64+n   <- W1[k][nc*64+n]
//  L2 kc=0..5 : base 147456 + kc*12288,   elem k*192+n  <- W2[kc*64+k][n]
//  L3 kc=0..2 : base 221184 + kc*12288,   elem k*192+n  <- W3[kc*64+k][n]
__global__ void wprep_kernel(const float* __restrict__ W1,
                             const float* __restrict__ W2,
                             const float* __restrict__ W3) {
    int e = blockIdx.x * blockDim.x + threadIdx.x;
    if (e >= 258048) return;
    float w;
    if (e < 147456) {
        int nc = e / 24576, r = e - nc * 24576;
        int k = r >> 6, n = r & 63;
        w = W1[k * 384 + nc * 64 + n];
    } else if (e < 221184) {
        int f = e - 147456;
        int kc = f / 12288, r = f - kc * 12288;
        int k = r / 192, n = r - k * 192;
        w = W2[(kc * 64 + k) * 192 + n];
    } else {
        int f = e - 221184;
        int kc = f / 12288, r = f - kc * 12288;
        int k = r / 192, n = r - k * 192;
        w = W3[(kc * 64 + k) * 192 + n];
    }
    g_Wprep[e] = __float2half(w);
}

// ---------------- kernel 3: register-A MLP + fused segment mean -------------
// SMEM: 4-slot weight ring, 4 x 55296 = 221184 bytes. Nothing else.
// chunk ids: 0-5 L1 ([384k][64n], row 144B), 6-11 L2, 12-14 L3 ([64k][192n], row 400B)
#define SMEM_BYTES 221184
#define SLOT 55296

__device__ __forceinline__ void issue_chunk(int id, uint32_t sB, int tid) {
    uint32_t dst = sB + (uint32_t)(id & 3) * SLOT;
    if (id < 6) {
        const __half* src = g_Wprep + (size_t)id * 24576;
        #pragma unroll
        for (int i = 0; i < 12; i++) {
            int idx = tid + i * 256;
            int row = idx >> 3, q = idx & 7;
            cp16(dst + row * 144 + q * 16, src + idx * 8);
        }
    } else if (id < 15) {
        const __half* src = g_Wprep + 147456 + (size_t)(id - 6) * 12288;
        #pragma unroll
        for (int i = 0; i < 6; i++) {
            int idx = tid + i * 256;
            int row = idx / 24, q = idx - row * 24;
            cp16(dst + row * 400 + q * 16, src + idx * 8);
        }
    }
    CP_COMMIT();   // empty group for id >= 15 keeps wait_group counting uniform
}

__global__ __launch_bounds__(256, 1)
void mlp_kernel(const int* __restrict__ edges,
                const float* __restrict__ b1,
                const float* __restrict__ b2,
                const float* __restrict__ b3,
                float* __restrict__ out)
{
    extern __shared__ char smem[];
    const uint32_t sB = smem_u32(smem);

    const int tid  = threadIdx.x;
    const int wid  = tid >> 5;
    const int lane = tid & 31;

    // ---- A-fragments straight from global (m16n8k16 A layout) ----
    const int e0    = blockIdx.x * 128;
    const int rbase = wid * 16 + (lane >> 2);     // row r0; r1 = r0 + 8
    const int cb    = (lane & 3) * 2;
    const int2 ed0 = *(const int2*)(edges + (size_t)(e0 + rbase) * 2);      // {dst, src}
    const int2 ed1 = *(const int2*)(edges + (size_t)(e0 + rbase + 8) * 2);
    const __half* xs0 = g_X + (size_t)ed0.y * HIDDEN;
    const __half* xd0 = g_X + (size_t)ed0.x * HIDDEN;
    const __half* xs1 = g_X + (size_t)ed1.y * HIDDEN;
    const __half* xd1 = g_X + (size_t)ed1.x * HIDDEN;

    uint32_t A[96];
    #pragma unroll
    for (int kt = 0; kt < 12; kt++) {             // k 0..191 -> x[src]
        int c = kt * 16 + cb;
        A[kt * 4 + 0] = *(const uint32_t*)(xs0 + c);
        A[kt * 4 + 1] = *(const uint32_t*)(xs1 + c);
        A[kt * 4 + 2] = *(const uint32_t*)(xs0 + c + 8);
        A[kt * 4 + 3] = *(const uint32_t*)(xs1 + c + 8);
    }
    #pragma unroll
    for (int kt = 12; kt < 24; kt++) {            // k 192..383 -> x[dst]
        int c = (kt - 12) * 16 + cb;
        A[kt * 4 + 0] = *(const uint32_t*)(xd0 + c);
        A[kt * 4 + 1] = *(const uint32_t*)(xd1 + c);
        A[kt * 4 + 2] = *(const uint32_t*)(xd0 + c + 8);
        A[kt * 4 + 3] = *(const uint32_t*)(xd1 + c + 8);
    }

    // ---- weight pipeline prologue ----
    issue_chunk(0, sB, tid);
    issue_chunk(1, sB, tid);
    issue_chunk(2, sB, tid);

    const uint32_t bo1 = (uint32_t)(lane & 15) * 144 + (uint32_t)(lane >> 4) * 16;
    const uint32_t bo2 = (uint32_t)(lane & 15) * 400 + (uint32_t)(lane >> 4) * 16;
    const int t2 = cb;

    uint32_t aH1[96];
    // ================= layer 1 =================
    #pragma unroll
    for (int c = 0; c < 6; c++) {
        CP_WAIT2();
        __syncthreads();
        float acc[8][4];
        #pragma unroll
        for (int j = 0; j < 8; j++)
            #pragma unroll
            for (int r = 0; r < 4; r++) acc[j][r] = 0.0f;

        const uint32_t bufB = sB + (uint32_t)(c & 3) * SLOT + bo1;
        #pragma unroll 4
        for (int kc = 0; kc < 24; kc++) {
            const uint32_t* a = &A[kc * 4];
            #pragma unroll
            for (int nt = 0; nt < 4; nt++) {
                uint32_t b[4];
                ldsm4t(b, bufB + kc * 2304 + nt * 32);
                mma16816(acc[2 * nt],     a, b[0], b[1]);
                mma16816(acc[2 * nt + 1], a, b[2], b[3]);
            }
        }
        issue_chunk(c + 3, sB, tid);

        #pragma unroll
        for (int kl = 0; kl < 4; kl++) {
            int j0 = 2 * kl, j1 = 2 * kl + 1;
            float2 bA = *(const float2*)&b1[c * 64 + j0 * 8 + t2];
            float2 bB = *(const float2*)&b1[c * 64 + j1 * 8 + t2];
            int ix = c * 16 + kl * 4;
            aH1[ix + 0] = packh2(gelu_exact(acc[j0][0] + bA.x), gelu_exact(acc[j0][1] + bA.y));
            aH1[ix + 1] = packh2(gelu_exact(acc[j0][2] + bA.x), gelu_exact(acc[j0][3] + bA.y));
            aH1[ix + 2] = packh2(gelu_exact(acc[j1][0] + bB.x), gelu_exact(acc[j1][1] + bB.y));
            aH1[ix + 3] = packh2(gelu_exact(acc[j1][2] + bB.x), gelu_exact(acc[j1][3] + bB.y));
        }
    }

    // ================= layer 2 =================
    float acc2[24][4];
    #pragma unroll
    for (int j = 0; j < 24; j++)
        #pragma unroll
        for (int r = 0; r < 4; r++) acc2[j][r] = 0.0f;

    #pragma unroll
    for (int cc = 0; cc < 6; cc++) {
        CP_WAIT2();
        __syncthreads();
        const uint32_t bufB = sB + (uint32_t)((6 + cc) & 3) * SLOT + bo2;
        #pragma unroll
        for (int kl = 0; kl < 4; kl++) {
            const uint32_t* a = &aH1[(4 * cc + kl) * 4];
            #pragma unroll
            for (int nt = 0; nt < 12; nt++) {
                uint32_t b[4];
                ldsm4t(b, bufB + kl * 6400 + nt * 32);
                mma16816(acc2[2 * nt],     a, b[0], b[1]);
                mma16816(acc2[2 * nt + 1], a, b[2], b[3]);
            }
        }
        issue_chunk(9 + cc, sB, tid);
    }

    uint32_t aH2[48];
    #pragma unroll
    for (int kl = 0; kl < 12; kl++) {
        int j0 = 2 * kl, j1 = 2 * kl + 1;
        float2 bA = *(const float2*)&b2[j0 * 8 + t2];
        float2 bB = *(const float2*)&b2[j1 * 8 + t2];
        aH2[kl * 4 + 0] = packh2(gelu_exact(acc2[j0][0] + bA.x), gelu_exact(acc2[j0][1] + bA.y));
        aH2[kl * 4 + 1] = packh2(gelu_exact(acc2[j0][2] + bA.x), gelu_exact(acc2[j0][3] + bA.y));
        aH2[kl * 4 + 2] = packh2(gelu_exact(acc2[j1][0] + bB.x), gelu_exact(acc2[j1][1] + bB.y));
        aH2[kl * 4 + 3] = packh2(gelu_exact(acc2[j1][2] + bB.x), gelu_exact(acc2[j1][3] + bB.y));
    }

    // ================= layer 3 =================
    float acc3[24][4];
    #pragma unroll
    for (int j = 0; j < 24; j++)
        #pragma unroll
        for (int r = 0; r < 4; r++) acc3[j][r] = 0.0f;

    #pragma unroll
    for (int cc = 0; cc < 3; cc++) {
        CP_WAIT2();
        __syncthreads();
        const uint32_t bufB = sB + (uint32_t)((12 + cc) & 3) * SLOT + bo2;
        #pragma unroll
        for (int kl = 0; kl < 4; kl++) {
            const uint32_t* a = &aH2[(4 * cc + kl) * 4];
            #pragma unroll
            for (int nt = 0; nt < 12; nt++) {
                uint32_t b[4];
                ldsm4t(b, bufB + kl * 6400 + nt * 32);
                mma16816(acc3[2 * nt],     a, b[0], b[1]);
                mma16816(acc3[2 * nt + 1], a, b[2], b[3]);
            }
        }
        issue_chunk(15 + cc, sB, tid);   // empty groups: keep wait counts uniform
    }

    // ===== fused segment mean: warp w == segment w =====
    #pragma unroll
    for (int tn = 0; tn < 24; tn++) {
        float s0 = acc3[tn][0] + acc3[tn][2];
        float s1 = acc3[tn][1] + acc3[tn][3];
        s0 += __shfl_xor_sync(0xFFFFFFFFu, s0, 4);
        s0 += __shfl_xor_sync(0xFFFFFFFFu, s0, 8);
        s0 += __shfl_xor_sync(0xFFFFFFFFu, s0, 16);
        s1 += __shfl_xor_sync(0xFFFFFFFFu, s1, 4);
        s1 += __shfl_xor_sync(0xFFFFFFFFu, s1, 8);
        s1 += __shfl_xor_sync(0xFFFFFFFFu, s1, 16);
        if (lane < 4) {
            int col = tn * 8 + lane * 2;
            float2 b = *(const float2*)&b3[col];
            float2 o;
            o.x = s0 * 0.0625f + b.x;
            o.y = s1 * 0.0625f + b.y;
            *(float2*)(out + (size_t)blockIdx.x * 1536 + wid * 192 + col) = o;
        }
    }
}

// ---------------- launch ----------------
extern "C" void kernel_launch(void* const* d_in, const int* in_sizes, int n_in,
                              void* d_out, int out_size) {
    const float* mesh_pos   = (const float*)d_in[0];
    const int*   mesh_edges = (const int*)d_in[1];
    const float* W1 = (const float*)d_in[3];
    const float* b1 = (const float*)d_in[4];
    const float* W2 = (const float*)d_in[5];
    const float* b2 = (const float*)d_in[6];
    const float* W3 = (const float*)d_in[7];
    const float* b3 = (const float*)d_in[8];
    float* out = (float*)d_out;

    cudaFuncSetAttribute(mlp_kernel, cudaFuncAttributeMaxDynamicSharedMemorySize, SMEM_BYTES);

    embed_kernel<<<(NNODES * 24 + 255) / 256, 256>>>(mesh_pos);
    wprep_kernel<<<(258048 + 255) / 256, 256>>>(W1, W2, W3);
    mlp_kernel<<<2048, 256, SMEM_BYTES>>>(mesh_edges, b1, b2, b3, out);
}

// round 10
// speedup vs baseline: 1.6740x; 1.0080x over previous
#include <cuda_runtime.h>
#include <cuda_fp16.h>
#include <cstdint>

#define HIDDEN 192
#define NNODES 262144

// ---------------- device scratch (no allocs allowed) ----------------
__device__ __half g_X[(size_t)NNODES * HIDDEN];     // node embeddings fp16
__device__ __align__(16) __half g_Wprep[258048];    // 15 chunk-contiguous weight pieces

// ---------------- helpers ----------------
__device__ __forceinline__ uint32_t smem_u32(const void* p) {
    uint32_t a;
    asm("{ .reg .u64 t; cvta.to.shared.u64 t, %1; cvt.u32.u64 %0, t; }" : "=r"(a) : "l"(p));
    return a;
}
__device__ __forceinline__ void cp16(uint32_t dst, const __half* src) {
    unsigned long long g = __cvta_generic_to_global(src);
    asm volatile("cp.async.cg.shared.global [%0], [%1], 16;" :: "r"(dst), "l"(g) : "memory");
}
#define CP_COMMIT() asm volatile("cp.async.commit_group;" ::: "memory")
#define CP_WAIT2()  asm volatile("cp.async.wait_group 2;" ::: "memory")

__device__ __forceinline__ void ldsm4t(uint32_t* r, uint32_t addr) {
    asm volatile("ldmatrix.sync.aligned.m8n8.x4.trans.shared.b16 {%0,%1,%2,%3}, [%4];"
        : "=r"(r[0]), "=r"(r[1]), "=r"(r[2]), "=r"(r[3]) : "r"(addr));
}
__device__ __forceinline__ void mma16816(float* d, const uint32_t* a, uint32_t b0, uint32_t b1) {
    asm volatile("mma.sync.aligned.m16n8k16.row.col.f32.f16.f16.f32 "
        "{%0,%1,%2,%3}, {%4,%5,%6,%7}, {%8,%9}, {%0,%1,%2,%3};"
        : "+f"(d[0]), "+f"(d[1]), "+f"(d[2]), "+f"(d[3])
        : "r"(a[0]), "r"(a[1]), "r"(a[2]), "r"(a[3]), "r"(b0), "r"(b1));
}
__device__ __forceinline__ float gelu_exact(float x) {
    return 0.5f * x * (1.0f + erff(x * 0.70710678118654752f));
}
__device__ __forceinline__ uint32_t packh2(float x, float y) {
    __half2 h = __floats2half2_rn(x, y);
    return *reinterpret_cast<uint32_t*>(&h);
}

// ---------------- kernel 1: sincos embedding (MUFU, 8B stores) --------------
__global__ void embed_kernel(const float* __restrict__ pos) {
    int idx = blockIdx.x * blockDim.x + threadIdx.x;
    if (idx >= NNODES * 24) return;
    int n = idx / 24;
    int t = idx - n * 24;
    int d = t >> 3, q = t & 7;
    int j0 = q * 4;
    float p = pos[n * 3 + d];
    float s[4], c[4];
    #pragma unroll
    for (int i = 0; i < 4; i++) {
        float omega = exp2f(-(float)(j0 + i) * (13.287712379549449f / 32.0f));
        __sincosf(p * omega, &s[i], &c[i]);
    }
    uint2 sv, cv;
    sv.x = packh2(s[0], s[1]); sv.y = packh2(s[2], s[3]);
    cv.x = packh2(c[0], c[1]); cv.y = packh2(c[2], c[3]);
    __half* xp = g_X + (size_t)n * HIDDEN + d * 64;
    *(uint2*)(xp + j0)      = sv;
    *(uint2*)(xp + 32 + j0) = cv;
}

// ---------------- kernel 2: weight prep (transpose into chunk layout) -------
//  L1 nc=0..5 : base nc*24576,            elem k*64+n   <- W1[k][nc*64+n]
//  L2 kc=0..5 : base 147456 + kc*12288,   elem k*192+n  <- W2[kc*64+k][n]
//  L3 kc=0..2 : base 221184 + kc*12288,   elem k*192+n  <- W3[kc*64+k][n]
__global__ void wprep_kernel(const float* __restrict__ W1,
                             const float* __restrict__ W2,
                             const float* __restrict__ W3) {
    int e = blockIdx.x * blockDim.x + threadIdx.x;
    if (e >= 258048) return;
    float w;
    if (e < 147456) {
        int nc = e / 24576, r = e - nc * 24576;
        int k = r >> 6, n = r & 63;
        w = W1[k * 384 + nc * 64 + n];
    } else if (e < 221184) {
        int f = e - 147456;
        int kc = f / 12288, r = f - kc * 12288;
        int k = r / 192, n = r - k * 192;
        w = W2[(kc * 64 + k) * 192 + n];
    } else {
        int f = e - 221184;
        int kc = f / 12288, r = f - kc * 12288;
        int k = r / 192, n = r - k * 192;
        w = W3[(kc * 64 + k) * 192 + n];
    }
    g_Wprep[e] = __float2half(w);
}

// ---------------- kernel 3: register-A MLP + fused segment mean -------------
// SMEM: 4-slot weight ring, 4 x 55296 = 221184 bytes. Nothing else.
// chunk ids: 0-5 L1 ([384k][64n], row 144B), 6-11 L2, 12-14 L3 ([64k][192n], row 400B)
#define SMEM_BYTES 221184
#define SLOT 55296

__device__ __forceinline__ void issue_chunk(int id, uint32_t sB, int tid) {
    uint32_t dst = sB + (uint32_t)(id & 3) * SLOT;
    if (id < 6) {
        const __half* src = g_Wprep + (size_t)id * 24576;
        #pragma unroll
        for (int i = 0; i < 12; i++) {
            int idx = tid + i * 256;
            int row = idx >> 3, q = idx & 7;
            cp16(dst + row * 144 + q * 16, src + idx * 8);
        }
    } else if (id < 15) {
        const __half* src = g_Wprep + 147456 + (size_t)(id - 6) * 12288;
        #pragma unroll
        for (int i = 0; i < 6; i++) {
            int idx = tid + i * 256;
            int row = idx / 24, q = idx - row * 24;
            cp16(dst + row * 400 + q * 16, src + idx * 8);
        }
    }
    CP_COMMIT();   // empty group for id >= 15 keeps wait_group counting uniform
}

__global__ __launch_bounds__(256, 1)
void mlp_kernel(const int* __restrict__ edges,
                const float* __restrict__ b1,
                const float* __restrict__ b2,
                const float* __restrict__ b3,
                float* __restrict__ out)
{
    extern __shared__ char smem[];
    const uint32_t sB = smem_u32(smem);

    const int tid  = threadIdx.x;
    const int wid  = tid >> 5;
    const int lane = tid & 31;

    // ---- A-fragments straight from global (m16n8k16 A layout) ----
    const int e0    = blockIdx.x * 128;
    const int rbase = wid * 16 + (lane >> 2);     // row r0; r1 = r0 + 8
    const int cb    = (lane & 3) * 2;
    const int2 ed0 = *(const int2*)(edges + (size_t)(e0 + rbase) * 2);      // {dst, src}
    const int2 ed1 = *(const int2*)(edges + (size_t)(e0 + rbase + 8) * 2);
    const __half* xs0 = g_X + (size_t)ed0.y * HIDDEN;
    const __half* xd0 = g_X + (size_t)ed0.x * HIDDEN;
    const __half* xs1 = g_X + (size_t)ed1.y * HIDDEN;
    const __half* xd1 = g_X + (size_t)ed1.x * HIDDEN;

    uint32_t A[96];
    #pragma unroll
    for (int kt = 0; kt < 12; kt++) {             // k 0..191 -> x[src]
        int c = kt * 16 + cb;
        A[kt * 4 + 0] = *(const uint32_t*)(xs0 + c);
        A[kt * 4 + 1] = *(const uint32_t*)(xs1 + c);
        A[kt * 4 + 2] = *(const uint32_t*)(xs0 + c + 8);
        A[kt * 4 + 3] = *(const uint32_t*)(xs1 + c + 8);
    }
    #pragma unroll
    for (int kt = 12; kt < 24; kt++) {            // k 192..383 -> x[dst]
        int c = (kt - 12) * 16 + cb;
        A[kt * 4 + 0] = *(const uint32_t*)(xd0 + c);
        A[kt * 4 + 1] = *(const uint32_t*)(xd1 + c);
        A[kt * 4 + 2] = *(const uint32_t*)(xd0 + c + 8);
        A[kt * 4 + 3] = *(const uint32_t*)(xd1 + c + 8);
    }

    // ---- weight pipeline prologue ----
    issue_chunk(0, sB, tid);
    issue_chunk(1, sB, tid);
    issue_chunk(2, sB, tid);

    const uint32_t bo1 = (uint32_t)(lane & 15) * 144 + (uint32_t)(lane >> 4) * 16;
    const uint32_t bo2 = (uint32_t)(lane & 15) * 400 + (uint32_t)(lane >> 4) * 16;
    const int t2 = cb;

    uint32_t aH1[96];
    // ================= layer 1 (pipelined B prefetch) =================
    #pragma unroll
    for (int c = 0; c < 6; c++) {
        CP_WAIT2();
        __syncthreads();
        float acc[8][4];
        #pragma unroll
        for (int j = 0; j < 8; j++)
            #pragma unroll
            for (int r = 0; r < 4; r++) acc[j][r] = 0.0f;

        const uint32_t bufB = sB + (uint32_t)(c & 3) * SLOT + bo1;
        uint32_t bf[2][4];
        ldsm4t(bf[0], bufB);                       // kc=0, nt=0
        #pragma unroll
        for (int kc = 0; kc < 24; kc++) {
            #pragma unroll
            for (int nt = 0; nt < 4; nt++) {
                const int cur = (kc * 4 + nt) & 1;
                if (!(kc == 23 && nt == 3)) {
                    int nkc = (nt == 3) ? kc + 1 : kc;
                    int nnt = (nt + 1) & 3;
                    ldsm4t(bf[cur ^ 1], bufB + nkc * 2304 + nnt * 32);
                }
                mma16816(acc[2 * nt],     &A[kc * 4], bf[cur][0], bf[cur][1]);
                mma16816(acc[2 * nt + 1], &A[kc * 4], bf[cur][2], bf[cur][3]);
            }
        }
        issue_chunk(c + 3, sB, tid);

        #pragma unroll
        for (int kl = 0; kl < 4; kl++) {
            int j0 = 2 * kl, j1 = 2 * kl + 1;
            float2 bA = *(const float2*)&b1[c * 64 + j0 * 8 + t2];
            float2 bB = *(const float2*)&b1[c * 64 + j1 * 8 + t2];
            int ix = c * 16 + kl * 4;
            aH1[ix + 0] = packh2(gelu_exact(acc[j0][0] + bA.x), gelu_exact(acc[j0][1] + bA.y));
            aH1[ix + 1] = packh2(gelu_exact(acc[j0][2] + bA.x), gelu_exact(acc[j0][3] + bA.y));
            aH1[ix + 2] = packh2(gelu_exact(acc[j1][0] + bB.x), gelu_exact(acc[j1][1] + bB.y));
            aH1[ix + 3] = packh2(gelu_exact(acc[j1][2] + bB.x), gelu_exact(acc[j1][3] + bB.y));
        }
    }

    // ================= layer 2 (pipelined) =================
    float acc2[24][4];
    #pragma unroll
    for (int j = 0; j < 24; j++)
        #pragma unroll
        for (int r = 0; r < 4; r++) acc2[j][r] = 0.0f;

    #pragma unroll
    for (int cc = 0; cc < 6; cc++) {
        CP_WAIT2();
        __syncthreads();
        const uint32_t bufB = sB + (uint32_t)((6 + cc) & 3) * SLOT + bo2;
        uint32_t bf[2][4];
        ldsm4t(bf[0], bufB);                       // kl=0, nt=0
        #pragma unroll
        for (int kl = 0; kl < 4; kl++) {
            const uint32_t* a = &aH1[(4 * cc + kl) * 4];
            #pragma unroll
            for (int nt = 0; nt < 12; nt++) {
                const int cur = (kl * 12 + nt) & 1;
                if (!(kl == 3 && nt == 11)) {
                    int nkl = (nt == 11) ? kl + 1 : kl;
                    int nnt = (nt == 11) ? 0 : nt + 1;
                    ldsm4t(bf[cur ^ 1], bufB + nkl * 6400 + nnt * 32);
                }
                mma16816(acc2[2 * nt],     a, bf[cur][0], bf[cur][1]);
                mma16816(acc2[2 * nt + 1], a, bf[cur][2], bf[cur][3]);
            }
        }
        issue_chunk(9 + cc, sB, tid);
    }

    uint32_t aH2[48];
    #pragma unroll
    for (int kl = 0; kl < 12; kl++) {
        int j0 = 2 * kl, j1 = 2 * kl + 1;
        float2 bA = *(const float2*)&b2[j0 * 8 + t2];
        float2 bB = *(const float2*)&b2[j1 * 8 + t2];
        aH2[kl * 4 + 0] = packh2(gelu_exact(acc2[j0][0] + bA.x), gelu_exact(acc2[j0][1] + bA.y));
        aH2[kl * 4 + 1] = packh2(gelu_exact(acc2[j0][2] + bA.x), gelu_exact(acc2[j0][3] + bA.y));
        aH2[kl * 4 + 2] = packh2(gelu_exact(acc2[j1][0] + bB.x), gelu_exact(acc2[j1][1] + bB.y));
        aH2[kl * 4 + 3] = packh2(gelu_exact(acc2[j1][2] + bB.x), gelu_exact(acc2[j1][3] + bB.y));
    }

    // ================= layer 3 (pipelined) =================
    float acc3[24][4];
    #pragma unroll
    for (int j = 0; j < 24; j++)
        #pragma unroll
        for (int r = 0; r < 4; r++) acc3[j][r] = 0.0f;

    #pragma unroll
    for (int cc = 0; cc < 3; cc++) {
        CP_WAIT2();
        __syncthreads();
        const uint32_t bufB = sB + (uint32_t)((12 + cc) & 3) * SLOT + bo2;
        uint32_t bf[2][4];
        ldsm4t(bf[0], bufB);
        #pragma unroll
        for (int kl = 0; kl < 4; kl++) {
            const uint32_t* a = &aH2[(4 * cc + kl) * 4];
            #pragma unroll
            for (int nt = 0; nt < 12; nt++) {
                const int cur = (kl * 12 + nt) & 1;
                if (!(kl == 3 && nt == 11)) {
                    int nkl = (nt == 11) ? kl + 1 : kl;
                    int nnt = (nt == 11) ? 0 : nt + 1;
                    ldsm4t(bf[cur ^ 1], bufB + nkl * 6400 + nnt * 32);
                }
                mma16816(acc3[2 * nt],     a, bf[cur][0], bf[cur][1]);
                mma16816(acc3[2 * nt + 1], a, bf[cur][2], bf[cur][3]);
            }
        }
        issue_chunk(15 + cc, sB, tid);   // empty groups: keep wait counts uniform
    }

    // ===== fused segment mean: warp w == segment w =====
    #pragma unroll
    for (int tn = 0; tn < 24; tn++) {
        float s0 = acc3[tn][0] + acc3[tn][2];
        float s1 = acc3[tn][1] + acc3[tn][3];
        s0 += __shfl_xor_sync(0xFFFFFFFFu, s0, 4);
        s0 += __shfl_xor_sync(0xFFFFFFFFu, s0, 8);
        s0 += __shfl_xor_sync(0xFFFFFFFFu, s0, 16);
        s1 += __shfl_xor_sync(0xFFFFFFFFu, s1, 4);
        s1 += __shfl_xor_sync(0xFFFFFFFFu, s1, 8);
        s1 += __shfl_xor_sync(0xFFFFFFFFu, s1, 16);
        if (lane < 4) {
            int col = tn * 8 + lane * 2;
            float2 b = *(const float2*)&b3[col];
            float2 o;
            o.x = s0 * 0.0625f + b.x;
            o.y = s1 * 0.0625f + b.y;
            *(float2*)(out + (size_t)blockIdx.x * 1536 + wid * 192 + col) = o;
        }
    }
}

// ---------------- launch ----------------
extern "C" void kernel_launch(void* const* d_in, const int* in_sizes, int n_in,
                              void* d_out, int out_size) {
    const float* mesh_pos   = (const float*)d_in[0];
    const int*   mesh_edges = (const int*)d_in[1];
    const float* W1 = (const float*)d_in[3];
    const float* b1 = (const float*)d_in[4];
    const float* W2 = (const float*)d_in[5];
    const float* b2 = (const float*)d_in[6];
    const float* W3 = (const float*)d_in[7];
    const float* b3 = (const float*)d_in[8];
    float* out = (float*)d_out;

    cudaFuncSetAttribute(mlp_kernel, cudaFuncAttributeMaxDynamicSharedMemorySize, SMEM_BYTES);

    embed_kernel<<<(NNODES * 24 + 255) / 256, 256>>>(mesh_pos);
    wprep_kernel<<<(258048 + 255) / 256, 256>>>(W1, W2, W3);
    mlp_kernel<<<2048, 256, SMEM_BYTES>>>(mesh_edges, b1, b2, b3, out);
}

// round 11
// speedup vs baseline: 1.9145x; 1.1437x over previous
#include <cuda_runtime.h>
#include <cuda_fp16.h>
#include <cstdint>

#define HIDDEN 192
#define NNODES 262144
#define NSEG   16384

// ---------------- device scratch (no allocs allowed) ----------------
__device__ __half g_X[(size_t)NNODES * HIDDEN];     // node embeddings fp16
__device__ __align__(16) __half g_Wprep[258048];    // swizzle-free chunked weights
__device__ float g_G[(size_t)NSEG * 384];           // per-segment dst partial (+b1)

// ---------------- helpers ----------------
__device__ __forceinline__ uint32_t smem_u32(const void* p) {
    uint32_t a;
    asm("{ .reg .u64 t; cvta.to.shared.u64 t, %1; cvt.u32.u64 %0, t; }" : "=r"(a) : "l"(p));
    return a;
}
__device__ __forceinline__ void cp16(uint32_t dst, const __half* src) {
    unsigned long long g = __cvta_generic_to_global(src);
    asm volatile("cp.async.cg.shared.global [%0], [%1], 16;" :: "r"(dst), "l"(g) : "memory");
}
#define CP_COMMIT() asm volatile("cp.async.commit_group;" ::: "memory")
#define CP_WAIT2()  asm volatile("cp.async.wait_group 2;" ::: "memory")

__device__ __forceinline__ void ldsm4t(uint32_t* r, uint32_t addr) {
    asm volatile("ldmatrix.sync.aligned.m8n8.x4.trans.shared.b16 {%0,%1,%2,%3}, [%4];"
        : "=r"(r[0]), "=r"(r[1]), "=r"(r[2]), "=r"(r[3]) : "r"(addr));
}
__device__ __forceinline__ void mma16816(float* d, const uint32_t* a, uint32_t b0, uint32_t b1) {
    asm volatile("mma.sync.aligned.m16n8k16.row.col.f32.f16.f16.f32 "
        "{%0,%1,%2,%3}, {%4,%5,%6,%7}, {%8,%9}, {%0,%1,%2,%3};"
        : "+f"(d[0]), "+f"(d[1]), "+f"(d[2]), "+f"(d[3])
        : "r"(a[0]), "r"(a[1]), "r"(a[2]), "r"(a[3]), "r"(b0), "r"(b1));
}
__device__ __forceinline__ float gelu_exact(float x) {
    return 0.5f * x * (1.0f + erff(x * 0.70710678118654752f));
}
__device__ __forceinline__ uint32_t packh2(float x, float y) {
    __half2 h = __floats2half2_rn(x, y);
    return *reinterpret_cast<uint32_t*>(&h);
}

// ---------------- kernel 1: sincos embedding (MUFU, 8B stores) --------------
__global__ void embed_kernel(const float* __restrict__ pos) {
    int idx = blockIdx.x * blockDim.x + threadIdx.x;
    if (idx >= NNODES * 24) return;
    int n = idx / 24;
    int t = idx - n * 24;
    int d = t >> 3, q = t & 7;
    int j0 = q * 4;
    float p = pos[n * 3 + d];
    float s[4], c[4];
    #pragma unroll
    for (int i = 0; i < 4; i++) {
        float omega = exp2f(-(float)(j0 + i) * (13.287712379549449f / 32.0f));
        __sincosf(p * omega, &s[i], &c[i]);
    }
    uint2 sv, cv;
    sv.x = packh2(s[0], s[1]); sv.y = packh2(s[2], s[3]);
    cv.x = packh2(c[0], c[1]); cv.y = packh2(c[2], c[3]);
    __half* xp = g_X + (size_t)n * HIDDEN + d * 64;
    *(uint2*)(xp + j0)      = sv;
    *(uint2*)(xp + 32 + j0) = cv;
}

// ---------------- kernel 2: weight prep -----------------------------------
// pieces of 12288 halfs each:
//  L1src p=0..5 : base p*12288,          k*64+n  <- W1[k][p*64+n]       (k 0..191)
//  L1dst p=0..5 : base 73728+p*12288,    k*64+n  <- W1[192+k][p*64+n]
//  L2    p=0..5 : base 147456+p*12288,   k*192+n <- W2[p*64+k][n]
//  L3    p=0..2 : base 221184+p*12288,   k*192+n <- W3[p*64+k][n]
__global__ void wprep_kernel(const float* __restrict__ W1,
                             const float* __restrict__ W2,
                             const float* __restrict__ W3) {
    int e = blockIdx.x * blockDim.x + threadIdx.x;
    if (e >= 258048) return;
    float w;
    if (e < 73728) {
        int p = e / 12288, r = e - p * 12288;
        int k = r >> 6, n = r & 63;
        w = W1[k * 384 + p * 64 + n];
    } else if (e < 147456) {
        int f = e - 73728;
        int p = f / 12288, r = f - p * 12288;
        int k = r >> 6, n = r & 63;
        w = W1[(192 + k) * 384 + p * 64 + n];
    } else if (e < 221184) {
        int f = e - 147456;
        int p = f / 12288, r = f - p * 12288;
        int k = r / 192, n = r - k * 192;
        w = W2[(p * 64 + k) * 192 + n];
    } else {
        int f = e - 221184;
        int p = f / 12288, r = f - p * 12288;
        int k = r / 192, n = r - k * 192;
        w = W3[(p * 64 + k) * 192 + n];
    }
    g_Wprep[e] = __float2half(w);
}

// ---------------- shared chunk loader --------------------------------------
// slot layout: narrow pieces ([192k][64n], row 144B) or wide ([64k][192n], row 400B)
#define SLOT 27648
#define SMEM_BYTES (4 * SLOT)   // 110592

// kind 0: narrow (L1 pieces), kind 1: wide (L2/L3)
__device__ __forceinline__ void issue_piece(uint32_t dst, const __half* src, int kind, int tid) {
    if (kind == 0) {
        #pragma unroll
        for (int i = 0; i < 6; i++) {
            int idx = tid + i * 256;
            int row = idx >> 3, q = idx & 7;
            cp16(dst + row * 144 + q * 16, src + idx * 8);
        }
    } else {
        #pragma unroll
        for (int i = 0; i < 6; i++) {
            int idx = tid + i * 256;
            int row = idx / 24, q = idx - row * 24;
            cp16(dst + row * 400 + q * 16, src + idx * 8);
        }
    }
    CP_COMMIT();
}

// ---------------- kernel 3: per-segment dst partial G ------------------------
// G[r][:] = x[r] @ W1_bot + b1,  r = 0..16383  (dst node id == segment id)
__global__ __launch_bounds__(256, 1)
void gpart_kernel(const float* __restrict__ b1) {
    extern __shared__ char smem[];
    const uint32_t sB = smem_u32(smem);
    const int tid  = threadIdx.x;
    const int wid  = tid >> 5;
    const int lane = tid & 31;

    const int rbase = blockIdx.x * 128 + wid * 16 + (lane >> 2);
    const int cb    = (lane & 3) * 2;
    const __half* x0 = g_X + (size_t)rbase * HIDDEN;
    const __half* x1 = g_X + (size_t)(rbase + 8) * HIDDEN;

    uint32_t A[48];
    #pragma unroll
    for (int kt = 0; kt < 12; kt++) {
        int c = kt * 16 + cb;
        A[kt * 4 + 0] = *(const uint32_t*)(x0 + c);
        A[kt * 4 + 1] = *(const uint32_t*)(x1 + c);
        A[kt * 4 + 2] = *(const uint32_t*)(x0 + c + 8);
        A[kt * 4 + 3] = *(const uint32_t*)(x1 + c + 8);
    }

    const __half* wsrc = g_Wprep + 73728;   // L1dst pieces
    issue_piece(sB + 0 * SLOT, wsrc + 0 * 12288, 0, tid);
    issue_piece(sB + 1 * SLOT, wsrc + 1 * 12288, 0, tid);
    issue_piece(sB + 2 * SLOT, wsrc + 2 * 12288, 0, tid);

    const uint32_t bo1 = (uint32_t)(lane & 15) * 144 + (uint32_t)(lane >> 4) * 16;

    #pragma unroll
    for (int c = 0; c < 6; c++) {
        CP_WAIT2();
        __syncthreads();
        float acc[8][4];
        #pragma unroll
        for (int j = 0; j < 8; j++)
            #pragma unroll
            for (int r = 0; r < 4; r++) acc[j][r] = 0.0f;

        const uint32_t bufB = sB + (uint32_t)(c & 3) * SLOT + bo1;
        #pragma unroll
        for (int kc = 0; kc < 12; kc++) {
            #pragma unroll
            for (int nt = 0; nt < 4; nt++) {
                uint32_t b[4];
                ldsm4t(b, bufB + kc * 2304 + nt * 32);
                mma16816(acc[2 * nt],     &A[kc * 4], b[0], b[1]);
                mma16816(acc[2 * nt + 1], &A[kc * 4], b[2], b[3]);
            }
        }
        if (c + 3 < 6) issue_piece(sB + (uint32_t)((c + 3) & 3) * SLOT, wsrc + (size_t)(c + 3) * 12288, 0, tid);
        else CP_COMMIT();

        #pragma unroll
        for (int j = 0; j < 8; j++) {
            int col = c * 64 + j * 8 + cb;
            float2 bb = *(const float2*)&b1[col];
            float2 o0, o1;
            o0.x = acc[j][0] + bb.x; o0.y = acc[j][1] + bb.y;
            o1.x = acc[j][2] + bb.x; o1.y = acc[j][3] + bb.y;
            *(float2*)&g_G[(size_t)rbase * 384 + col]       = o0;
            *(float2*)&g_G[(size_t)(rbase + 8) * 384 + col] = o1;
        }
    }
}

// ---------------- kernel 4: main MLP (src-half L1 + G init) -----------------
// chunks: 0-5 L1src (narrow), 6-11 L2 (wide), 12-14 L3 (wide)
__device__ __forceinline__ void issue_chunk(int id, uint32_t sB, int tid) {
    uint32_t dst = sB + (uint32_t)(id & 3) * SLOT;
    if (id < 6)       issue_piece(dst, g_Wprep + (size_t)id * 12288, 0, tid);
    else if (id < 15) issue_piece(dst, g_Wprep + 147456 + (size_t)(id - 6) * 12288, 1, tid);
    else CP_COMMIT();
}

__global__ __launch_bounds__(256, 1)
void mlp_kernel(const int* __restrict__ edges,
                const float* __restrict__ b2,
                const float* __restrict__ b3,
                float* __restrict__ out)
{
    extern __shared__ char smem[];
    const uint32_t sB = smem_u32(smem);

    const int tid  = threadIdx.x;
    const int wid  = tid >> 5;
    const int lane = tid & 31;

    // ---- A-fragments (src half only) straight from global ----
    const int e0    = blockIdx.x * 128;
    const int rbase = wid * 16 + (lane >> 2);
    const int cb    = (lane & 3) * 2;
    const int src0 = edges[(size_t)(e0 + rbase) * 2 + 1];
    const int src1 = edges[(size_t)(e0 + rbase + 8) * 2 + 1];
    const __half* xs0 = g_X + (size_t)src0 * HIDDEN;
    const __half* xs1 = g_X + (size_t)src1 * HIDDEN;

    uint32_t A[48];
    #pragma unroll
    for (int kt = 0; kt < 12; kt++) {
        int c = kt * 16 + cb;
        A[kt * 4 + 0] = *(const uint32_t*)(xs0 + c);
        A[kt * 4 + 1] = *(const uint32_t*)(xs1 + c);
        A[kt * 4 + 2] = *(const uint32_t*)(xs0 + c + 8);
        A[kt * 4 + 3] = *(const uint32_t*)(xs1 + c + 8);
    }

    issue_chunk(0, sB, tid);
    issue_chunk(1, sB, tid);
    issue_chunk(2, sB, tid);

    const uint32_t bo1 = (uint32_t)(lane & 15) * 144 + (uint32_t)(lane >> 4) * 16;
    const uint32_t bo2 = (uint32_t)(lane & 15) * 400 + (uint32_t)(lane >> 4) * 16;
    const int t2 = cb;
    const int seg = blockIdx.x * 8 + wid;                 // warp == segment
    const float* gp = g_G + (size_t)seg * 384;

    uint32_t aH1[96];
    // ================= layer 1 (src half, K=192; acc init = G) =================
    #pragma unroll
    for (int c = 0; c < 6; c++) {
        CP_WAIT2();
        __syncthreads();
        float acc[8][4];
        #pragma unroll
        for (int j = 0; j < 8; j++) {
            float2 gv = *(const float2*)(gp + c * 64 + j * 8 + t2);
            acc[j][0] = gv.x; acc[j][1] = gv.y;
            acc[j][2] = gv.x; acc[j][3] = gv.y;
        }

        const uint32_t bufB = sB + (uint32_t)(c & 3) * SLOT + bo1;
        #pragma unroll
        for (int kc = 0; kc < 12; kc++) {
            #pragma unroll
            for (int nt = 0; nt < 4; nt++) {
                uint32_t b[4];
                ldsm4t(b, bufB + kc * 2304 + nt * 32);
                mma16816(acc[2 * nt],     &A[kc * 4], b[0], b[1]);
                mma16816(acc[2 * nt + 1], &A[kc * 4], b[2], b[3]);
            }
        }
        issue_chunk(c + 3, sB, tid);

        // epilogue: gelu (bias already inside G) -> A-fragments for layer 2
        #pragma unroll
        for (int kl = 0; kl < 4; kl++) {
            int j0 = 2 * kl, j1 = 2 * kl + 1;
            int ix = c * 16 + kl * 4;
            aH1[ix + 0] = packh2(gelu_exact(acc[j0][0]), gelu_exact(acc[j0][1]));
            aH1[ix + 1] = packh2(gelu_exact(acc[j0][2]), gelu_exact(acc[j0][3]));
            aH1[ix + 2] = packh2(gelu_exact(acc[j1][0]), gelu_exact(acc[j1][1]));
            aH1[ix + 3] = packh2(gelu_exact(acc[j1][2]), gelu_exact(acc[j1][3]));
        }
    }

    // ================= layer 2 =================
    float acc2[24][4];
    #pragma unroll
    for (int j = 0; j < 24; j++)
        #pragma unroll
        for (int r = 0; r < 4; r++) acc2[j][r] = 0.0f;

    #pragma unroll
    for (int cc = 0; cc < 6; cc++) {
        CP_WAIT2();
        __syncthreads();
        const uint32_t bufB = sB + (uint32_t)((6 + cc) & 3) * SLOT + bo2;
        #pragma unroll
        for (int kl = 0; kl < 4; kl++) {
            const uint32_t* a = &aH1[(4 * cc + kl) * 4];
            #pragma unroll
            for (int nt = 0; nt < 12; nt++) {
                uint32_t b[4];
                ldsm4t(b, bufB + kl * 6400 + nt * 32);
                mma16816(acc2[2 * nt],     a, b[0], b[1]);
                mma16816(acc2[2 * nt + 1], a, b[2], b[3]);
            }
        }
        issue_chunk(9 + cc, sB, tid);
    }

    uint32_t aH2[48];
    #pragma unroll
    for (int kl = 0; kl < 12; kl++) {
        int j0 = 2 * kl, j1 = 2 * kl + 1;
        float2 bA = *(const float2*)&b2[j0 * 8 + t2];
        float2 bB = *(const float2*)&b2[j1 * 8 + t2];
        aH2[kl * 4 + 0] = packh2(gelu_exact(acc2[j0][0] + bA.x), gelu_exact(acc2[j0][1] + bA.y));
        aH2[kl * 4 + 1] = packh2(gelu_exact(acc2[j0][2] + bA.x), gelu_exact(acc2[j0][3] + bA.y));
        aH2[kl * 4 + 2] = packh2(gelu_exact(acc2[j1][0] + bB.x), gelu_exact(acc2[j1][1] + bB.y));
        aH2[kl * 4 + 3] = packh2(gelu_exact(acc2[j1][2] + bB.x), gelu_exact(acc2[j1][3] + bB.y));
    }

    // ================= layer 3 =================
    float acc3[24][4];
    #pragma unroll
    for (int j = 0; j < 24; j++)
        #pragma unroll
        for (int r = 0; r < 4; r++) acc3[j][r] = 0.0f;

    #pragma unroll
    for (int cc = 0; cc < 3; cc++) {
        CP_WAIT2();
        __syncthreads();
        const uint32_t bufB = sB + (uint32_t)((12 + cc) & 3) * SLOT + bo2;
        #pragma unroll
        for (int kl = 0; kl < 4; kl++) {
            const uint32_t* a = &aH2[(4 * cc + kl) * 4];
            #pragma unroll
            for (int nt = 0; nt < 12; nt++) {
                uint32_t b[4];
                ldsm4t(b, bufB + kl * 6400 + nt * 32);
                mma16816(acc3[2 * nt],     a, b[0], b[1]);
                mma16816(acc3[2 * nt + 1], a, b[2], b[3]);
            }
        }
        issue_chunk(15 + cc, sB, tid);
    }

    // ===== fused segment mean: warp w == segment w =====
    #pragma unroll
    for (int tn = 0; tn < 24; tn++) {
        float s0 = acc3[tn][0] + acc3[tn][2];
        float s1 = acc3[tn][1] + acc3[tn][3];
        s0 += __shfl_xor_sync(0xFFFFFFFFu, s0, 4);
        s0 += __shfl_xor_sync(0xFFFFFFFFu, s0, 8);
        s0 += __shfl_xor_sync(0xFFFFFFFFu, s0, 16);
        s1 += __shfl_xor_sync(0xFFFFFFFFu, s1, 4);
        s1 += __shfl_xor_sync(0xFFFFFFFFu, s1, 8);
        s1 += __shfl_xor_sync(0xFFFFFFFFu, s1, 16);
        if (lane < 4) {
            int col = tn * 8 + lane * 2;
            float2 b = *(const float2*)&b3[col];
            float2 o;
            o.x = s0 * 0.0625f + b.x;
            o.y = s1 * 0.0625f + b.y;
            *(float2*)(out + (size_t)blockIdx.x * 1536 + wid * 192 + col) = o;
        }
    }
}

// ---------------- launch ----------------
extern "C" void kernel_launch(void* const* d_in, const int* in_sizes, int n_in,
                              void* d_out, int out_size) {
    const float* mesh_pos   = (const float*)d_in[0];
    const int*   mesh_edges = (const int*)d_in[1];
    const float* W1 = (const float*)d_in[3];
    const float* b1 = (const float*)d_in[4];
    const float* W2 = (const float*)d_in[5];
    const float* b2 = (const float*)d_in[6];
    const float* W3 = (const float*)d_in[7];
    const float* b3 = (const float*)d_in[8];
    float* out = (float*)d_out;

    cudaFuncSetAttribute(gpart_kernel, cudaFuncAttributeMaxDynamicSharedMemorySize, SMEM_BYTES);
    cudaFuncSetAttribute(mlp_kernel,   cudaFuncAttributeMaxDynamicSharedMemorySize, SMEM_BYTES);

    embed_kernel<<<(NNODES * 24 + 255) / 256, 256>>>(mesh_pos);
    wprep_kernel<<<(258048 + 255) / 256, 256>>>(W1, W2, W3);
    gpart_kernel<<<NSEG / 128, 256, SMEM_BYTES>>>(b1);
    mlp_kernel<<<2048, 256, SMEM_BYTES>>>(mesh_edges, b2, b3, out);
}

// round 12
// speedup vs baseline: 2.6265x; 1.3719x over previous
#include <cuda_runtime.h>
#include <cuda_fp16.h>
#include <cstdint>

#define HIDDEN 192
#define NNODES 262144
#define NSEG   16384

// ---------------- device scratch (no allocs allowed) ----------------
__device__ __half g_X[(size_t)NNODES * HIDDEN];     // node embeddings fp16
__device__ __align__(16) __half g_Wprep[258048];    // chunked weights
__device__ float g_G[(size_t)NSEG * 384];           // per-segment dst partial (+b1)

// ---------------- helpers ----------------
__device__ __forceinline__ uint32_t smem_u32(const void* p) {
    uint32_t a;
    asm("{ .reg .u64 t; cvta.to.shared.u64 t, %1; cvt.u32.u64 %0, t; }" : "=r"(a) : "l"(p));
    return a;
}
__device__ __forceinline__ void cp16(uint32_t dst, const __half* src) {
    unsigned long long g = __cvta_generic_to_global(src);
    asm volatile("cp.async.cg.shared.global [%0], [%1], 16;" :: "r"(dst), "l"(g) : "memory");
}
#define CP_COMMIT() asm volatile("cp.async.commit_group;" ::: "memory")
#define CP_WAIT2()  asm volatile("cp.async.wait_group 2;" ::: "memory")

__device__ __forceinline__ void ldsm4(uint32_t* r, uint32_t addr) {
    asm volatile("ldmatrix.sync.aligned.m8n8.x4.shared.b16 {%0,%1,%2,%3}, [%4];"
        : "=r"(r[0]), "=r"(r[1]), "=r"(r[2]), "=r"(r[3]) : "r"(addr));
}
__device__ __forceinline__ void ldsm4t(uint32_t* r, uint32_t addr) {
    asm volatile("ldmatrix.sync.aligned.m8n8.x4.trans.shared.b16 {%0,%1,%2,%3}, [%4];"
        : "=r"(r[0]), "=r"(r[1]), "=r"(r[2]), "=r"(r[3]) : "r"(addr));
}
__device__ __forceinline__ void mma16816(float* d, const uint32_t* a, uint32_t b0, uint32_t b1) {
    asm volatile("mma.sync.aligned.m16n8k16.row.col.f32.f16.f16.f32 "
        "{%0,%1,%2,%3}, {%4,%5,%6,%7}, {%8,%9}, {%0,%1,%2,%3};"
        : "+f"(d[0]), "+f"(d[1]), "+f"(d[2]), "+f"(d[3])
        : "r"(a[0]), "r"(a[1]), "r"(a[2]), "r"(a[3]), "r"(b0), "r"(b1));
}
__device__ __forceinline__ float gelu_exact(float x) {
    return 0.5f * x * (1.0f + erff(x * 0.70710678118654752f));
}
__device__ __forceinline__ uint32_t packh2(float x, float y) {
    __half2 h = __floats2half2_rn(x, y);
    return *reinterpret_cast<uint32_t*>(&h);
}

// ---------------- kernel 1: sincos embedding ----------------
__global__ void embed_kernel(const float* __restrict__ pos) {
    int idx = blockIdx.x * blockDim.x + threadIdx.x;
    if (idx >= NNODES * 24) return;
    int n = idx / 24;
    int t = idx - n * 24;
    int d = t >> 3, q = t & 7;
    int j0 = q * 4;
    float p = pos[n * 3 + d];
    float s[4], c[4];
    #pragma unroll
    for (int i = 0; i < 4; i++) {
        float omega = exp2f(-(float)(j0 + i) * (13.287712379549449f / 32.0f));
        __sincosf(p * omega, &s[i], &c[i]);
    }
    uint2 sv, cv;
    sv.x = packh2(s[0], s[1]); sv.y = packh2(s[2], s[3]);
    cv.x = packh2(c[0], c[1]); cv.y = packh2(c[2], c[3]);
    __half* xp = g_X + (size_t)n * HIDDEN + d * 64;
    *(uint2*)(xp + j0)      = sv;
    *(uint2*)(xp + 32 + j0) = cv;
}

// ---------------- kernel 2: weight prep (unchanged layouts) ----------------
__global__ void wprep_kernel(const float* __restrict__ W1,
                             const float* __restrict__ W2,
                             const float* __restrict__ W3) {
    int e = blockIdx.x * blockDim.x + threadIdx.x;
    if (e >= 258048) return;
    float w;
    if (e < 73728) {
        int p = e / 12288, r = e - p * 12288;
        int k = r >> 6, n = r & 63;
        w = W1[k * 384 + p * 64 + n];
    } else if (e < 147456) {
        int f = e - 73728;
        int p = f / 12288, r = f - p * 12288;
        int k = r >> 6, n = r & 63;
        w = W1[(192 + k) * 384 + p * 64 + n];
    } else if (e < 221184) {
        int f = e - 147456;
        int p = f / 12288, r = f - p * 12288;
        int k = r / 192, n = r - k * 192;
        w = W2[(p * 64 + k) * 192 + n];
    } else {
        int f = e - 221184;
        int p = f / 12288, r = f - p * 12288;
        int k = r / 192, n = r - k * 192;
        w = W3[(p * 64 + k) * 192 + n];
    }
    g_Wprep[e] = __float2half(w);
}

#define SLOT 27648
#define SMEM_G (4 * SLOT)                 // gpart smem
#define H1OFF  (4 * SLOT)                 // 110592
#define SMEM_MLP (H1OFF + 100352)         // 210944

// 256-thread loader (gpart)
__device__ __forceinline__ void issue_piece256(uint32_t dst, const __half* src, int tid) {
    #pragma unroll
    for (int i = 0; i < 6; i++) {
        int idx = tid + i * 256;
        int row = idx >> 3, q = idx & 7;
        cp16(dst + row * 144 + q * 16, src + idx * 8);
    }
    CP_COMMIT();
}
// 512-thread loader (mlp): kind 0 narrow (144B row), kind 1 wide (400B row)
__device__ __forceinline__ void issue_chunk512(int id, uint32_t sB, int tid) {
    uint32_t dst = sB + (uint32_t)(id & 3) * SLOT;
    if (id < 6) {
        const __half* src = g_Wprep + (size_t)id * 12288;
        #pragma unroll
        for (int i = 0; i < 3; i++) {
            int idx = tid + i * 512;
            int row = idx >> 3, q = idx & 7;
            cp16(dst + row * 144 + q * 16, src + idx * 8);
        }
    } else if (id < 15) {
        const __half* src = g_Wprep + 147456 + (size_t)(id - 6) * 12288;
        #pragma unroll
        for (int i = 0; i < 3; i++) {
            int idx = tid + i * 512;
            int row = idx / 24, q = idx - row * 24;
            cp16(dst + row * 400 + q * 16, src + idx * 8);
        }
    }
    CP_COMMIT();
}

// ---------------- kernel 3: per-segment dst partial G (unchanged) -----------
__global__ __launch_bounds__(256, 1)
void gpart_kernel(const float* __restrict__ b1) {
    extern __shared__ char smem[];
    const uint32_t sB = smem_u32(smem);
    const int tid  = threadIdx.x;
    const int wid  = tid >> 5;
    const int lane = tid & 31;

    const int rbase = blockIdx.x * 128 + wid * 16 + (lane >> 2);
    const int cb    = (lane & 3) * 2;
    const __half* x0 = g_X + (size_t)rbase * HIDDEN;
    const __half* x1 = g_X + (size_t)(rbase + 8) * HIDDEN;

    uint32_t A[48];
    #pragma unroll
    for (int kt = 0; kt < 12; kt++) {
        int c = kt * 16 + cb;
        A[kt * 4 + 0] = *(const uint32_t*)(x0 + c);
        A[kt * 4 + 1] = *(const uint32_t*)(x1 + c);
        A[kt * 4 + 2] = *(const uint32_t*)(x0 + c + 8);
        A[kt * 4 + 3] = *(const uint32_t*)(x1 + c + 8);
    }

    const __half* wsrc = g_Wprep + 73728;
    issue_piece256(sB + 0 * SLOT, wsrc + 0 * 12288, tid);
    issue_piece256(sB + 1 * SLOT, wsrc + 1 * 12288, tid);
    issue_piece256(sB + 2 * SLOT, wsrc + 2 * 12288, tid);

    const uint32_t bo1 = (uint32_t)(lane & 15) * 144 + (uint32_t)(lane >> 4) * 16;

    #pragma unroll
    for (int c = 0; c < 6; c++) {
        CP_WAIT2();
        __syncthreads();
        float acc[8][4];
        #pragma unroll
        for (int j = 0; j < 8; j++)
            #pragma unroll
            for (int r = 0; r < 4; r++) acc[j][r] = 0.0f;

        const uint32_t bufB = sB + (uint32_t)(c & 3) * SLOT + bo1;
        #pragma unroll
        for (int kc = 0; kc < 12; kc++) {
            #pragma unroll
            for (int nt = 0; nt < 4; nt++) {
                uint32_t b[4];
                ldsm4t(b, bufB + kc * 2304 + nt * 32);
                mma16816(acc[2 * nt],     &A[kc * 4], b[0], b[1]);
                mma16816(acc[2 * nt + 1], &A[kc * 4], b[2], b[3]);
            }
        }
        if (c + 3 < 6) issue_piece256(sB + (uint32_t)((c + 3) & 3) * SLOT, wsrc + (size_t)(c + 3) * 12288, tid);
        else CP_COMMIT();

        #pragma unroll
        for (int j = 0; j < 8; j++) {
            int col = c * 64 + j * 8 + cb;
            float2 bb = *(const float2*)&b1[col];
            float2 o0, o1;
            o0.x = acc[j][0] + bb.x; o0.y = acc[j][1] + bb.y;
            o1.x = acc[j][2] + bb.x; o1.y = acc[j][3] + bb.y;
            *(float2*)&g_G[(size_t)rbase * 384 + col]       = o0;
            *(float2*)&g_G[(size_t)(rbase + 8) * 384 + col] = o1;
        }
    }
}

// ---------------- kernel 4: main MLP, 512 threads, N-split warp pairs -------
__global__ __launch_bounds__(512, 1)
void mlp_kernel(const int* __restrict__ edges,
                const float* __restrict__ b2,
                const float* __restrict__ b3,
                float* __restrict__ out)
{
    extern __shared__ char smem[];
    const uint32_t sB  = smem_u32(smem);
    const uint32_t h1a = sB + H1OFF;                 // h1: 128 x 392 halfs; h2: 128 x 200 halfs (alias)

    const int tid  = threadIdx.x;
    const int wid  = tid >> 5;
    const int lane = tid & 31;
    const int rg   = wid >> 1;        // row group 0..7 (= segment within CTA)
    const int ch   = wid & 1;         // N column half

    // ---- L1 A-fragments (src half) from global ----
    const int e0    = blockIdx.x * 128;
    const int rbase = rg * 16 + (lane >> 2);
    const int cb    = (lane & 3) * 2;
    const int src0 = edges[(size_t)(e0 + rbase) * 2 + 1];
    const int src1 = edges[(size_t)(e0 + rbase + 8) * 2 + 1];
    const __half* xs0 = g_X + (size_t)src0 * HIDDEN;
    const __half* xs1 = g_X + (size_t)src1 * HIDDEN;

    uint32_t A[48];
    #pragma unroll
    for (int kt = 0; kt < 12; kt++) {
        int c = kt * 16 + cb;
        A[kt * 4 + 0] = *(const uint32_t*)(xs0 + c);
        A[kt * 4 + 1] = *(const uint32_t*)(xs1 + c);
        A[kt * 4 + 2] = *(const uint32_t*)(xs0 + c + 8);
        A[kt * 4 + 3] = *(const uint32_t*)(xs1 + c + 8);
    }

    issue_chunk512(0, sB, tid);
    issue_chunk512(1, sB, tid);
    issue_chunk512(2, sB, tid);

    const uint32_t bo1 = (uint32_t)(lane & 15) * 144 + (uint32_t)(lane >> 4) * 16;
    const uint32_t bo2 = (uint32_t)(lane & 15) * 400 + (uint32_t)(lane >> 4) * 16;
    const int seg = blockIdx.x * 8 + rg;
    const float* gp = g_G + (size_t)seg * 384;

    const int r0 = rbase;            // rows this thread owns
    const int r1 = rbase + 8;

    // ================= layer 1: K=192 (src), acc init = G; h1 -> smem ======
    #pragma unroll
    for (int c = 0; c < 6; c++) {
        CP_WAIT2();
        __syncthreads();
        float acc[4][4];
        #pragma unroll
        for (int j2 = 0; j2 < 4; j2++) {
            float2 gv = *(const float2*)(gp + c * 64 + ch * 32 + j2 * 8 + cb);
            acc[j2][0] = gv.x; acc[j2][1] = gv.y;
            acc[j2][2] = gv.x; acc[j2][3] = gv.y;
        }
        const uint32_t bufB = sB + (uint32_t)(c & 3) * SLOT + bo1;
        #pragma unroll
        for (int kc = 0; kc < 12; kc++) {
            #pragma unroll
            for (int lt = 0; lt < 2; lt++) {
                uint32_t b[4];
                ldsm4t(b, bufB + kc * 2304 + (ch * 2 + lt) * 32);
                mma16816(acc[2 * lt],     &A[kc * 4], b[0], b[1]);
                mma16816(acc[2 * lt + 1], &A[kc * 4], b[2], b[3]);
            }
        }
        issue_chunk512(c + 3, sB, tid);

        // epilogue: gelu -> h1 smem (stride 392 halfs)
        #pragma unroll
        for (int j2 = 0; j2 < 4; j2++) {
            int col = c * 64 + ch * 32 + j2 * 8 + cb;
            *(uint32_t*)(smem + H1OFF + (r0 * 392 + col) * 2) =
                packh2(gelu_exact(acc[j2][0]), gelu_exact(acc[j2][1]));
            *(uint32_t*)(smem + H1OFF + (r1 * 392 + col) * 2) =
                packh2(gelu_exact(acc[j2][2]), gelu_exact(acc[j2][3]));
        }
    }

    // ================= layer 2: K=384 from h1 smem =================
    float acc2[12][4];
    #pragma unroll
    for (int j = 0; j < 12; j++)
        #pragma unroll
        for (int r = 0; r < 4; r++) acc2[j][r] = 0.0f;

    const uint32_t aBase1 = h1a + ((uint32_t)(rg * 16 + (lane & 15)) * 392 + (uint32_t)(lane >> 4) * 8) * 2;
    #pragma unroll
    for (int cc = 0; cc < 6; cc++) {
        CP_WAIT2();
        __syncthreads();
        const uint32_t bufB = sB + (uint32_t)((6 + cc) & 3) * SLOT + bo2;
        #pragma unroll
        for (int kl = 0; kl < 4; kl++) {
            uint32_t a[4];
            ldsm4(a, aBase1 + (uint32_t)(cc * 64 + kl * 16) * 2);
            #pragma unroll
            for (int lt = 0; lt < 6; lt++) {
                uint32_t b[4];
                ldsm4t(b, bufB + kl * 6400 + (ch * 6 + lt) * 32);
                mma16816(acc2[2 * lt],     a, b[0], b[1]);
                mma16816(acc2[2 * lt + 1], a, b[2], b[3]);
            }
        }
        issue_chunk512(9 + cc, sB, tid);
    }

    // h2 -> smem (reuse h1 region, stride 200 halfs). Sync: L2 reads done first.
    __syncthreads();
    #pragma unroll
    for (int lt = 0; lt < 6; lt++) {
        int j0 = 2 * lt, j1 = 2 * lt + 1;
        int col0 = ch * 96 + lt * 16 + cb;
        float2 bA = *(const float2*)&b2[col0];
        float2 bB = *(const float2*)&b2[col0 + 8];
        *(uint32_t*)(smem + H1OFF + (r0 * 200 + col0) * 2) =
            packh2(gelu_exact(acc2[j0][0] + bA.x), gelu_exact(acc2[j0][1] + bA.y));
        *(uint32_t*)(smem + H1OFF + (r1 * 200 + col0) * 2) =
            packh2(gelu_exact(acc2[j0][2] + bA.x), gelu_exact(acc2[j0][3] + bA.y));
        *(uint32_t*)(smem + H1OFF + (r0 * 200 + col0 + 8) * 2) =
            packh2(gelu_exact(acc2[j1][0] + bB.x), gelu_exact(acc2[j1][1] + bB.y));
        *(uint32_t*)(smem + H1OFF + (r1 * 200 + col0 + 8) * 2) =
            packh2(gelu_exact(acc2[j1][2] + bB.x), gelu_exact(acc2[j1][3] + bB.y));
    }

    // ================= layer 3: K=192 from h2 smem =================
    float acc3[12][4];
    #pragma unroll
    for (int j = 0; j < 12; j++)
        #pragma unroll
        for (int r = 0; r < 4; r++) acc3[j][r] = 0.0f;

    const uint32_t aBase2 = h1a + ((uint32_t)(rg * 16 + (lane & 15)) * 200 + (uint32_t)(lane >> 4) * 8) * 2;
    #pragma unroll
    for (int cc = 0; cc < 3; cc++) {
        CP_WAIT2();
        __syncthreads();
        const uint32_t bufB = sB + (uint32_t)((12 + cc) & 3) * SLOT + bo2;
        #pragma unroll
        for (int kl = 0; kl < 4; kl++) {
            uint32_t a[4];
            ldsm4(a, aBase2 + (uint32_t)(cc * 64 + kl * 16) * 2);
            #pragma unroll
            for (int lt = 0; lt < 6; lt++) {
                uint32_t b[4];
                ldsm4t(b, bufB + kl * 6400 + (ch * 6 + lt) * 32);
                mma16816(acc3[2 * lt],     a, b[0], b[1]);
                mma16816(acc3[2 * lt + 1], a, b[2], b[3]);
            }
        }
        issue_chunk512(15 + cc, sB, tid);
    }

    // ===== fused segment mean (warp pair: rg = segment, ch = col half) =====
    #pragma unroll
    for (int tn = 0; tn < 12; tn++) {
        float s0 = acc3[tn][0] + acc3[tn][2];
        float s1 = acc3[tn][1] + acc3[tn][3];
        s0 += __shfl_xor_sync(0xFFFFFFFFu, s0, 4);
        s0 += __shfl_xor_sync(0xFFFFFFFFu, s0, 8);
        s0 += __shfl_xor_sync(0xFFFFFFFFu, s0, 16);
        s1 += __shfl_xor_sync(0xFFFFFFFFu, s1, 4);
        s1 += __shfl_xor_sync(0xFFFFFFFFu, s1, 8);
        s1 += __shfl_xor_sync(0xFFFFFFFFu, s1, 16);
        if (lane < 4) {
            int col = ch * 96 + tn * 8 + lane * 2;
            float2 b = *(const float2*)&b3[col];
            float2 o;
            o.x = s0 * 0.0625f + b.x;
            o.y = s1 * 0.0625f + b.y;
            *(float2*)(out + (size_t)blockIdx.x * 1536 + rg * 192 + col) = o;
        }
    }
}

// ---------------- launch ----------------
extern "C" void kernel_launch(void* const* d_in, const int* in_sizes, int n_in,
                              void* d_out, int out_size) {
    const float* mesh_pos   = (const float*)d_in[0];
    const int*   mesh_edges = (const int*)d_in[1];
    const float* W1 = (const float*)d_in[3];
    const float* b1 = (const float*)d_in[4];
    const float* W2 = (const float*)d_in[5];
    const float* b2 = (const float*)d_in[6];
    const float* W3 = (const float*)d_in[7];
    const float* b3 = (const float*)d_in[8];
    float* out = (float*)d_out;

    cudaFuncSetAttribute(gpart_kernel, cudaFuncAttributeMaxDynamicSharedMemorySize, SMEM_G);
    cudaFuncSetAttribute(mlp_kernel,   cudaFuncAttributeMaxDynamicSharedMemorySize, SMEM_MLP);

    embed_kernel<<<(NNODES * 24 + 255) / 256, 256>>>(mesh_pos);
    wprep_kernel<<<(258048 + 255) / 256, 256>>>(W1, W2, W3);
    gpart_kernel<<<NSEG / 128, 256, SMEM_G>>>(b1);
    mlp_kernel<<<2048, 512, SMEM_MLP>>>(mesh_edges, b2, b3, out);
}

// round 13
// speedup vs baseline: 2.8043x; 1.0677x over previous
#include <cuda_runtime.h>
#include <cuda_fp16.h>
#include <cstdint>

#define HIDDEN 192
#define NNODES 262144
#define NSEG   16384

// ---------------- device scratch (no allocs allowed) ----------------
__device__ __half g_X[(size_t)NNODES * HIDDEN];     // node embeddings fp16
__device__ __align__(16) __half g_Wprep[258048];    // chunked weights
__device__ float g_G[(size_t)NSEG * 384];           // per-segment dst partial (+b1)

// ---------------- helpers ----------------
__device__ __forceinline__ uint32_t smem_u32(const void* p) {
    uint32_t a;
    asm("{ .reg .u64 t; cvta.to.shared.u64 t, %1; cvt.u32.u64 %0, t; }" : "=r"(a) : "l"(p));
    return a;
}
__device__ __forceinline__ void cp16(uint32_t dst, const __half* src) {
    unsigned long long g = __cvta_generic_to_global(src);
    asm volatile("cp.async.cg.shared.global [%0], [%1], 16;" :: "r"(dst), "l"(g) : "memory");
}
#define CP_COMMIT() asm volatile("cp.async.commit_group;" ::: "memory")
#define CP_WAIT2()  asm volatile("cp.async.wait_group 2;" ::: "memory")

__device__ __forceinline__ void ldsm4(uint32_t* r, uint32_t addr) {
    asm volatile("ldmatrix.sync.aligned.m8n8.x4.shared.b16 {%0,%1,%2,%3}, [%4];"
        : "=r"(r[0]), "=r"(r[1]), "=r"(r[2]), "=r"(r[3]) : "r"(addr));
}
__device__ __forceinline__ void ldsm4t(uint32_t* r, uint32_t addr) {
    asm volatile("ldmatrix.sync.aligned.m8n8.x4.trans.shared.b16 {%0,%1,%2,%3}, [%4];"
        : "=r"(r[0]), "=r"(r[1]), "=r"(r[2]), "=r"(r[3]) : "r"(addr));
}
__device__ __forceinline__ void mma16816(float* d, const uint32_t* a, uint32_t b0, uint32_t b1) {
    asm volatile("mma.sync.aligned.m16n8k16.row.col.f32.f16.f16.f32 "
        "{%0,%1,%2,%3}, {%4,%5,%6,%7}, {%8,%9}, {%0,%1,%2,%3};"
        : "+f"(d[0]), "+f"(d[1]), "+f"(d[2]), "+f"(d[3])
        : "r"(a[0]), "r"(a[1]), "r"(a[2]), "r"(a[3]), "r"(b0), "r"(b1));
}
__device__ __forceinline__ float gelu_exact(float x) {
    return 0.5f * x * (1.0f + erff(x * 0.70710678118654752f));
}
__device__ __forceinline__ uint32_t packh2(float x, float y) {
    __half2 h = __floats2half2_rn(x, y);
    return *reinterpret_cast<uint32_t*>(&h);
}

// ---------------- kernel 1: fused embed + weight prep ----------------
#define EMB_BLOCKS 24576          // NNODES*24/256
#define WPR_BLOCKS 1008           // ceil(258048/256)
__global__ void prep_kernel(const float* __restrict__ pos,
                            const float* __restrict__ W1,
                            const float* __restrict__ W2,
                            const float* __restrict__ W3) {
    int b = blockIdx.x;
    if (b < EMB_BLOCKS) {
        int idx = b * 256 + threadIdx.x;
        int n = idx / 24;
        int t = idx - n * 24;
        int d = t >> 3, q = t & 7;
        int j0 = q * 4;
        float p = pos[n * 3 + d];
        float s[4], c[4];
        #pragma unroll
        for (int i = 0; i < 4; i++) {
            float omega = exp2f(-(float)(j0 + i) * (13.287712379549449f / 32.0f));
            __sincosf(p * omega, &s[i], &c[i]);
        }
        uint2 sv, cv;
        sv.x = packh2(s[0], s[1]); sv.y = packh2(s[2], s[3]);
        cv.x = packh2(c[0], c[1]); cv.y = packh2(c[2], c[3]);
        __half* xp = g_X + (size_t)n * HIDDEN + d * 64;
        *(uint2*)(xp + j0)      = sv;
        *(uint2*)(xp + 32 + j0) = cv;
    } else {
        int e = (b - EMB_BLOCKS) * 256 + threadIdx.x;
        if (e >= 258048) return;
        float w;
        if (e < 73728) {
            int p = e / 12288, r = e - p * 12288;
            int k = r >> 6, n = r & 63;
            w = W1[k * 384 + p * 64 + n];
        } else if (e < 147456) {
            int f = e - 73728;
            int p = f / 12288, r = f - p * 12288;
            int k = r >> 6, n = r & 63;
            w = W1[(192 + k) * 384 + p * 64 + n];
        } else if (e < 221184) {
            int f = e - 147456;
            int p = f / 12288, r = f - p * 12288;
            int k = r / 192, n = r - k * 192;
            w = W2[(p * 64 + k) * 192 + n];
        } else {
            int f = e - 221184;
            int p = f / 12288, r = f - p * 12288;
            int k = r / 192, n = r - k * 192;
            w = W3[(p * 64 + k) * 192 + n];
        }
        g_Wprep[e] = __float2half(w);
    }
}

#define SLOT 27648
#define SMEM_G (4 * SLOT)
#define H1OFF  (4 * SLOT)                 // 110592
#define SMEM_MLP (H1OFF + 100352)         // 210944

__device__ __forceinline__ void issue_piece256(uint32_t dst, const __half* src, int tid) {
    #pragma unroll
    for (int i = 0; i < 6; i++) {
        int idx = tid + i * 256;
        int row = idx >> 3, q = idx & 7;
        cp16(dst + row * 144 + q * 16, src + idx * 8);
    }
    CP_COMMIT();
}
__device__ __forceinline__ void issue_chunk512(int id, uint32_t sB, int tid) {
    uint32_t dst = sB + (uint32_t)(id & 3) * SLOT;
    if (id < 6) {
        const __half* src = g_Wprep + (size_t)id * 12288;
        #pragma unroll
        for (int i = 0; i < 3; i++) {
            int idx = tid + i * 512;
            int row = idx >> 3, q = idx & 7;
            cp16(dst + row * 144 + q * 16, src + idx * 8);
        }
    } else if (id < 15) {
        const __half* src = g_Wprep + 147456 + (size_t)(id - 6) * 12288;
        #pragma unroll
        for (int i = 0; i < 3; i++) {
            int idx = tid + i * 512;
            int row = idx / 24, q = idx - row * 24;
            cp16(dst + row * 400 + q * 16, src + idx * 8);
        }
    }
    CP_COMMIT();
}

// ---------------- kernel 2: per-segment dst partial G ------------------------
__global__ __launch_bounds__(256, 1)
void gpart_kernel(const float* __restrict__ b1) {
    extern __shared__ char smem[];
    const uint32_t sB = smem_u32(smem);
    const int tid  = threadIdx.x;
    const int wid  = tid >> 5;
    const int lane = tid & 31;

    const int rbase = blockIdx.x * 128 + wid * 16 + (lane >> 2);
    const int cb    = (lane & 3) * 2;
    const __half* x0 = g_X + (size_t)rbase * HIDDEN;
    const __half* x1 = g_X + (size_t)(rbase + 8) * HIDDEN;

    uint32_t A[48];
    #pragma unroll
    for (int kt = 0; kt < 12; kt++) {
        int c = kt * 16 + cb;
        A[kt * 4 + 0] = *(const uint32_t*)(x0 + c);
        A[kt * 4 + 1] = *(const uint32_t*)(x1 + c);
        A[kt * 4 + 2] = *(const uint32_t*)(x0 + c + 8);
        A[kt * 4 + 3] = *(const uint32_t*)(x1 + c + 8);
    }

    const __half* wsrc = g_Wprep + 73728;
    issue_piece256(sB + 0 * SLOT, wsrc + 0 * 12288, tid);
    issue_piece256(sB + 1 * SLOT, wsrc + 1 * 12288, tid);
    issue_piece256(sB + 2 * SLOT, wsrc + 2 * 12288, tid);

    const uint32_t bo1 = (uint32_t)(lane & 15) * 144 + (uint32_t)(lane >> 4) * 16;

    #pragma unroll
    for (int c = 0; c < 6; c++) {
        CP_WAIT2();
        __syncthreads();
        float acc[8][4];
        #pragma unroll
        for (int j = 0; j < 8; j++)
            #pragma unroll
            for (int r = 0; r < 4; r++) acc[j][r] = 0.0f;

        const uint32_t bufB = sB + (uint32_t)(c & 3) * SLOT + bo1;
        #pragma unroll
        for (int kc = 0; kc < 12; kc++) {
            #pragma unroll
            for (int nt = 0; nt < 4; nt++) {
                uint32_t b[4];
                ldsm4t(b, bufB + kc * 2304 + nt * 32);
                mma16816(acc[2 * nt],     &A[kc * 4], b[0], b[1]);
                mma16816(acc[2 * nt + 1], &A[kc * 4], b[2], b[3]);
            }
        }
        if (c + 3 < 6) issue_piece256(sB + (uint32_t)((c + 3) & 3) * SLOT, wsrc + (size_t)(c + 3) * 12288, tid);
        else CP_COMMIT();

        #pragma unroll
        for (int j = 0; j < 8; j++) {
            int col = c * 64 + j * 8 + cb;
            float2 bb = *(const float2*)&b1[col];
            float2 o0, o1;
            o0.x = acc[j][0] + bb.x; o0.y = acc[j][1] + bb.y;
            o1.x = acc[j][2] + bb.x; o1.y = acc[j][3] + bb.y;
            *(float2*)&g_G[(size_t)rbase * 384 + col]       = o0;
            *(float2*)&g_G[(size_t)(rbase + 8) * 384 + col] = o1;
        }
    }
}

// ---------------- kernel 3: main MLP ----------------------------------------
// L1: warp = (rg 0..7 [16 rows], ch 0..1 [32 of 64 cols per chunk])
// L2/L3: warp = (rg2 0..3 [32 rows], ch2 0..3 [48 cols])
__global__ __launch_bounds__(512, 1)
void mlp_kernel(const int* __restrict__ edges,
                const float* __restrict__ b2,
                const float* __restrict__ b3,
                float* __restrict__ out)
{
    extern __shared__ char smem[];
    const uint32_t sB  = smem_u32(smem);
    const uint32_t h1a = sB + H1OFF;

    const int tid  = threadIdx.x;
    const int wid  = tid >> 5;
    const int lane = tid & 31;
    const int rg   = wid >> 1;
    const int ch   = wid & 1;

    // ---- L1 A-fragments (src half) from global ----
    const int e0    = blockIdx.x * 128;
    const int rbase = rg * 16 + (lane >> 2);
    const int cb    = (lane & 3) * 2;
    const int src0 = edges[(size_t)(e0 + rbase) * 2 + 1];
    const int src1 = edges[(size_t)(e0 + rbase + 8) * 2 + 1];
    const __half* xs0 = g_X + (size_t)src0 * HIDDEN;
    const __half* xs1 = g_X + (size_t)src1 * HIDDEN;

    uint32_t A[48];
    #pragma unroll
    for (int kt = 0; kt < 12; kt++) {
        int c = kt * 16 + cb;
        A[kt * 4 + 0] = *(const uint32_t*)(xs0 + c);
        A[kt * 4 + 1] = *(const uint32_t*)(xs1 + c);
        A[kt * 4 + 2] = *(const uint32_t*)(xs0 + c + 8);
        A[kt * 4 + 3] = *(const uint32_t*)(xs1 + c + 8);
    }

    issue_chunk512(0, sB, tid);
    issue_chunk512(1, sB, tid);
    issue_chunk512(2, sB, tid);

    const uint32_t bo1 = (uint32_t)(lane & 15) * 144 + (uint32_t)(lane >> 4) * 16;
    const uint32_t bo2 = (uint32_t)(lane & 15) * 400 + (uint32_t)(lane >> 4) * 16;
    const int seg = blockIdx.x * 8 + rg;
    const float* gp = g_G + (size_t)seg * 384;

    const int r0 = rbase;
    const int r1 = rbase + 8;

    // ================= layer 1: K=192 (src), acc init = G; h1 -> smem ======
    #pragma unroll
    for (int c = 0; c < 6; c++) {
        CP_WAIT2();
        __syncthreads();
        float acc[4][4];
        #pragma unroll
        for (int j2 = 0; j2 < 4; j2++) {
            float2 gv = *(const float2*)(gp + c * 64 + ch * 32 + j2 * 8 + cb);
            acc[j2][0] = gv.x; acc[j2][1] = gv.y;
            acc[j2][2] = gv.x; acc[j2][3] = gv.y;
        }
        const uint32_t bufB = sB + (uint32_t)(c & 3) * SLOT + bo1;
        #pragma unroll
        for (int kc = 0; kc < 12; kc++) {
            #pragma unroll
            for (int lt = 0; lt < 2; lt++) {
                uint32_t b[4];
                ldsm4t(b, bufB + kc * 2304 + (ch * 2 + lt) * 32);
                mma16816(acc[2 * lt],     &A[kc * 4], b[0], b[1]);
                mma16816(acc[2 * lt + 1], &A[kc * 4], b[2], b[3]);
            }
        }
        issue_chunk512(c + 3, sB, tid);

        #pragma unroll
        for (int j2 = 0; j2 < 4; j2++) {
            int col = c * 64 + ch * 32 + j2 * 8 + cb;
            *(uint32_t*)(smem + H1OFF + (r0 * 392 + col) * 2) =
                packh2(gelu_exact(acc[j2][0]), gelu_exact(acc[j2][1]));
            *(uint32_t*)(smem + H1OFF + (r1 * 392 + col) * 2) =
                packh2(gelu_exact(acc[j2][2]), gelu_exact(acc[j2][3]));
        }
    }

    // ---- re-map warps for L2/L3: (4 rg2 x 4 ch2) ----
    const int rg2 = wid >> 2;          // 0..3, rows rg2*32..+31
    const int ch2 = wid & 3;           // 0..3, cols ch2*48..+47
    const uint32_t aB1 = h1a + (((uint32_t)(rg2 * 32 + (lane & 15))) * 392 + (uint32_t)(lane >> 4) * 8) * 2;

    // ================= layer 2: K=384 from h1 smem =================
    float acc2[2][6][4];
    #pragma unroll
    for (int m = 0; m < 2; m++)
        #pragma unroll
        for (int n = 0; n < 6; n++)
            #pragma unroll
            for (int r = 0; r < 4; r++) acc2[m][n][r] = 0.0f;

    #pragma unroll
    for (int cc = 0; cc < 6; cc++) {
        CP_WAIT2();
        __syncthreads();
        const uint32_t bufB = sB + (uint32_t)((6 + cc) & 3) * SLOT + bo2;
        #pragma unroll
        for (int kl = 0; kl < 4; kl++) {
            uint32_t a0[4], a1[4];
            ldsm4(a0, aB1 + (uint32_t)(cc * 64 + kl * 16) * 2);
            ldsm4(a1, aB1 + (uint32_t)(16 * 392 + cc * 64 + kl * 16) * 2);
            #pragma unroll
            for (int lt = 0; lt < 3; lt++) {
                uint32_t b[4];
                ldsm4t(b, bufB + kl * 6400 + (ch2 * 3 + lt) * 32);
                mma16816(acc2[0][2 * lt],     a0, b[0], b[1]);
                mma16816(acc2[0][2 * lt + 1], a0, b[2], b[3]);
                mma16816(acc2[1][2 * lt],     a1, b[0], b[1]);
                mma16816(acc2[1][2 * lt + 1], a1, b[2], b[3]);
            }
        }
        issue_chunk512(9 + cc, sB, tid);
    }

    // h2 -> smem (reuse h1 region, stride 200 halfs)
    __syncthreads();
    #pragma unroll
    for (int m = 0; m < 2; m++) {
        int ra = rg2 * 32 + m * 16 + (lane >> 2);
        int rb = ra + 8;
        #pragma unroll
        for (int n = 0; n < 6; n++) {
            int col = ch2 * 48 + n * 8 + cb;
            float2 bb = *(const float2*)&b2[col];
            *(uint32_t*)(smem + H1OFF + (ra * 200 + col) * 2) =
                packh2(gelu_exact(acc2[m][n][0] + bb.x), gelu_exact(acc2[m][n][1] + bb.y));
            *(uint32_t*)(smem + H1OFF + (rb * 200 + col) * 2) =
                packh2(gelu_exact(acc2[m][n][2] + bb.x), gelu_exact(acc2[m][n][3] + bb.y));
        }
    }

    // ================= layer 3: K=192 from h2 smem =================
    float acc3[2][6][4];
    #pragma unroll
    for (int m = 0; m < 2; m++)
        #pragma unroll
        for (int n = 0; n < 6; n++)
            #pragma unroll
            for (int r = 0; r < 4; r++) acc3[m][n][r] = 0.0f;

    const uint32_t aB2 = h1a + (((uint32_t)(rg2 * 32 + (lane & 15))) * 200 + (uint32_t)(lane >> 4) * 8) * 2;
    #pragma unroll
    for (int cc = 0; cc < 3; cc++) {
        CP_WAIT2();
        __syncthreads();
        const uint32_t bufB = sB + (uint32_t)((12 + cc) & 3) * SLOT + bo2;
        #pragma unroll
        for (int kl = 0; kl < 4; kl++) {
            uint32_t a0[4], a1[4];
            ldsm4(a0, aB2 + (uint32_t)(cc * 64 + kl * 16) * 2);
            ldsm4(a1, aB2 + (uint32_t)(16 * 200 + cc * 64 + kl * 16) * 2);
            #pragma unroll
            for (int lt = 0; lt < 3; lt++) {
                uint32_t b[4];
                ldsm4t(b, bufB + kl * 6400 + (ch2 * 3 + lt) * 32);
                mma16816(acc3[0][2 * lt],     a0, b[0], b[1]);
                mma16816(acc3[0][2 * lt + 1], a0, b[2], b[3]);
                mma16816(acc3[1][2 * lt],     a1, b[0], b[1]);
                mma16816(acc3[1][2 * lt + 1], a1, b[2], b[3]);
            }
        }
        issue_chunk512(15 + cc, sB, tid);
    }

    // ===== fused segment mean: warp owns 2 segments (m) x 48 cols (ch2) =====
    #pragma unroll
    for (int m = 0; m < 2; m++) {
        #pragma unroll
        for (int n = 0; n < 6; n++) {
            float s0 = acc3[m][n][0] + acc3[m][n][2];
            float s1 = acc3[m][n][1] + acc3[m][n][3];
            s0 += __shfl_xor_sync(0xFFFFFFFFu, s0, 4);
            s0 += __shfl_xor_sync(0xFFFFFFFFu, s0, 8);
            s0 += __shfl_xor_sync(0xFFFFFFFFu, s0, 16);
            s1 += __shfl_xor_sync(0xFFFFFFFFu, s1, 4);
            s1 += __shfl_xor_sync(0xFFFFFFFFu, s1, 8);
            s1 += __shfl_xor_sync(0xFFFFFFFFu, s1, 16);
            if (lane < 4) {
                int col = ch2 * 48 + n * 8 + lane * 2;
                float2 b = *(const float2*)&b3[col];
                float2 o;
                o.x = s0 * 0.0625f + b.x;
                o.y = s1 * 0.0625f + b.y;
                *(float2*)(out + (size_t)blockIdx.x * 1536 + (rg2 * 2 + m) * 192 + col) = o;
            }
        }
    }
}

// ---------------- launch ----------------
extern "C" void kernel_launch(void* const* d_in, const int* in_sizes, int n_in,
                              void* d_out, int out_size) {
    const float* mesh_pos   = (const float*)d_in[0];
    const int*   mesh_edges = (const int*)d_in[1];
    const float* W1 = (const float*)d_in[3];
    const float* b1 = (const float*)d_in[4];
    const float* W2 = (const float*)d_in[5];
    const float* b2 = (const float*)d_in[6];
    const float* W3 = (const float*)d_in[7];
    const float* b3 = (const float*)d_in[8];
    float* out = (float*)d_out;

    cudaFuncSetAttribute(gpart_kernel, cudaFuncAttributeMaxDynamicSharedMemorySize, SMEM_G);
    cudaFuncSetAttribute(mlp_kernel,   cudaFuncAttributeMaxDynamicSharedMemorySize, SMEM_MLP);

    prep_kernel<<<EMB_BLOCKS + WPR_BLOCKS, 256>>>(mesh_pos, W1, W2, W3);
    gpart_kernel<<<NSEG / 128, 256, SMEM_G>>>(b1);
    mlp_kernel<<<2048, 512, SMEM_MLP>>>(mesh_edges, b2, b3, out);
}

// round 14
// speedup vs baseline: 3.0460x; 1.0862x over previous
#include <cuda_runtime.h>
#include <cuda_fp16.h>
#include <cstdint>

#define HIDDEN 192
#define NNODES 262144
#define NSEG   16384

// ---------------- device scratch (no allocs allowed) ----------------
__device__ __half g_X[(size_t)NNODES * HIDDEN];     // node embeddings fp16
__device__ __align__(16) __half g_Wprep[258048];    // chunked weights
__device__ float g_G[(size_t)NSEG * 384];           // per-segment dst partial (+b1)

// ---------------- helpers ----------------
__device__ __forceinline__ uint32_t smem_u32(const void* p) {
    uint32_t a;
    asm("{ .reg .u64 t; cvta.to.shared.u64 t, %1; cvt.u32.u64 %0, t; }" : "=r"(a) : "l"(p));
    return a;
}
__device__ __forceinline__ void cp16(uint32_t dst, const __half* src) {
    unsigned long long g = __cvta_generic_to_global(src);
    asm volatile("cp.async.cg.shared.global [%0], [%1], 16;" :: "r"(dst), "l"(g) : "memory");
}
#define CP_COMMIT() asm volatile("cp.async.commit_group;" ::: "memory")
#define CP_WAIT2()  asm volatile("cp.async.wait_group 2;" ::: "memory")
#define CP_WAIT0()  asm volatile("cp.async.wait_group 0;" ::: "memory")

__device__ __forceinline__ void ldsm4(uint32_t* r, uint32_t addr) {
    asm volatile("ldmatrix.sync.aligned.m8n8.x4.shared.b16 {%0,%1,%2,%3}, [%4];"
        : "=r"(r[0]), "=r"(r[1]), "=r"(r[2]), "=r"(r[3]) : "r"(addr));
}
__device__ __forceinline__ void ldsm4t(uint32_t* r, uint32_t addr) {
    asm volatile("ldmatrix.sync.aligned.m8n8.x4.trans.shared.b16 {%0,%1,%2,%3}, [%4];"
        : "=r"(r[0]), "=r"(r[1]), "=r"(r[2]), "=r"(r[3]) : "r"(addr));
}
__device__ __forceinline__ void mma16816(float* d, const uint32_t* a, uint32_t b0, uint32_t b1) {
    asm volatile("mma.sync.aligned.m16n8k16.row.col.f32.f16.f16.f32 "
        "{%0,%1,%2,%3}, {%4,%5,%6,%7}, {%8,%9}, {%0,%1,%2,%3};"
        : "+f"(d[0]), "+f"(d[1]), "+f"(d[2]), "+f"(d[3])
        : "r"(a[0]), "r"(a[1]), "r"(a[2]), "r"(a[3]), "r"(b0), "r"(b1));
}
__device__ __forceinline__ float gelu_exact(float x) {
    return 0.5f * x * (1.0f + erff(x * 0.70710678118654752f));
}
__device__ __forceinline__ uint32_t packh2(float x, float y) {
    __half2 h = __floats2half2_rn(x, y);
    return *reinterpret_cast<uint32_t*>(&h);
}

// ---------------- kernel 1: fused embed + weight prep ----------------
#define EMB_BLOCKS 24576
#define WPR_BLOCKS 1008
__global__ void prep_kernel(const float* __restrict__ pos,
                            const float* __restrict__ W1,
                            const float* __restrict__ W2,
                            const float* __restrict__ W3) {
    int b = blockIdx.x;
    if (b < EMB_BLOCKS) {
        int idx = b * 256 + threadIdx.x;
        int n = idx / 24;
        int t = idx - n * 24;
        int d = t >> 3, q = t & 7;
        int j0 = q * 4;
        float p = pos[n * 3 + d];
        float s[4], c[4];
        #pragma unroll
        for (int i = 0; i < 4; i++) {
            float omega = exp2f(-(float)(j0 + i) * (13.287712379549449f / 32.0f));
            __sincosf(p * omega, &s[i], &c[i]);
        }
        uint2 sv, cv;
        sv.x = packh2(s[0], s[1]); sv.y = packh2(s[2], s[3]);
        cv.x = packh2(c[0], c[1]); cv.y = packh2(c[2], c[3]);
        __half* xp = g_X + (size_t)n * HIDDEN + d * 64;
        *(uint2*)(xp + j0)      = sv;
        *(uint2*)(xp + 32 + j0) = cv;
    } else {
        int e = (b - EMB_BLOCKS) * 256 + threadIdx.x;
        if (e >= 258048) return;
        float w;
        if (e < 73728) {
            int p = e / 12288, r = e - p * 12288;
            int k = r >> 6, n = r & 63;
            w = W1[k * 384 + p * 64 + n];
        } else if (e < 147456) {
            int f = e - 73728;
            int p = f / 12288, r = f - p * 12288;
            int k = r >> 6, n = r & 63;
            w = W1[(192 + k) * 384 + p * 64 + n];
        } else if (e < 221184) {
            int f = e - 147456;
            int p = f / 12288, r = f - p * 12288;
            int k = r / 192, n = r - k * 192;
            w = W2[(p * 64 + k) * 192 + n];
        } else {
            int f = e - 221184;
            int p = f / 12288, r = f - p * 12288;
            int k = r / 192, n = r - k * 192;
            w = W3[(p * 64 + k) * 192 + n];
        }
        g_Wprep[e] = __float2half(w);
    }
}

#define SLOT 27648
#define SMEM_G (4 * SLOT)
#define H1OFF  (4 * SLOT)                 // 110592
#define H2MOFF (H1OFF + 100352)           // 210944: h2 segment means, 16 x 200 halfs
#define SMEM_MLP (H2MOFF + 6400)          // 217344

__device__ __forceinline__ void issue_piece256(uint32_t dst, const __half* src, int tid) {
    #pragma unroll
    for (int i = 0; i < 6; i++) {
        int idx = tid + i * 256;
        int row = idx >> 3, q = idx & 7;
        cp16(dst + row * 144 + q * 16, src + idx * 8);
    }
    CP_COMMIT();
}
__device__ __forceinline__ void issue_chunk512(int id, uint32_t sB, int tid) {
    uint32_t dst = sB + (uint32_t)(id & 3) * SLOT;
    if (id < 6) {
        const __half* src = g_Wprep + (size_t)id * 12288;
        #pragma unroll
        for (int i = 0; i < 3; i++) {
            int idx = tid + i * 512;
            int row = idx >> 3, q = idx & 7;
            cp16(dst + row * 144 + q * 16, src + idx * 8);
        }
    } else if (id < 15) {
        const __half* src = g_Wprep + 147456 + (size_t)(id - 6) * 12288;
        #pragma unroll
        for (int i = 0; i < 3; i++) {
            int idx = tid + i * 512;
            int row = idx / 24, q = idx - row * 24;
            cp16(dst + row * 400 + q * 16, src + idx * 8);
        }
    }
    CP_COMMIT();
}

// ---------------- kernel 2: per-segment dst partial G ------------------------
__global__ __launch_bounds__(256, 1)
void gpart_kernel(const float* __restrict__ b1) {
    extern __shared__ char smem[];
    const uint32_t sB = smem_u32(smem);
    const int tid  = threadIdx.x;
    const int wid  = tid >> 5;
    const int lane = tid & 31;

    const int rbase = blockIdx.x * 128 + wid * 16 + (lane >> 2);
    const int cb    = (lane & 3) * 2;
    const __half* x0 = g_X + (size_t)rbase * HIDDEN;
    const __half* x1 = g_X + (size_t)(rbase + 8) * HIDDEN;

    uint32_t A[48];
    #pragma unroll
    for (int kt = 0; kt < 12; kt++) {
        int c = kt * 16 + cb;
        A[kt * 4 + 0] = *(const uint32_t*)(x0 + c);
        A[kt * 4 + 1] = *(const uint32_t*)(x1 + c);
        A[kt * 4 + 2] = *(const uint32_t*)(x0 + c + 8);
        A[kt * 4 + 3] = *(const uint32_t*)(x1 + c + 8);
    }

    const __half* wsrc = g_Wprep + 73728;
    issue_piece256(sB + 0 * SLOT, wsrc + 0 * 12288, tid);
    issue_piece256(sB + 1 * SLOT, wsrc + 1 * 12288, tid);
    issue_piece256(sB + 2 * SLOT, wsrc + 2 * 12288, tid);

    const uint32_t bo1 = (uint32_t)(lane & 15) * 144 + (uint32_t)(lane >> 4) * 16;

    #pragma unroll
    for (int c = 0; c < 6; c++) {
        CP_WAIT2();
        __syncthreads();
        float acc[8][4];
        #pragma unroll
        for (int j = 0; j < 8; j++)
            #pragma unroll
            for (int r = 0; r < 4; r++) acc[j][r] = 0.0f;

        const uint32_t bufB = sB + (uint32_t)(c & 3) * SLOT + bo1;
        #pragma unroll
        for (int kc = 0; kc < 12; kc++) {
            #pragma unroll
            for (int nt = 0; nt < 4; nt++) {
                uint32_t b[4];
                ldsm4t(b, bufB + kc * 2304 + nt * 32);
                mma16816(acc[2 * nt],     &A[kc * 4], b[0], b[1]);
                mma16816(acc[2 * nt + 1], &A[kc * 4], b[2], b[3]);
            }
        }
        if (c + 3 < 6) issue_piece256(sB + (uint32_t)((c + 3) & 3) * SLOT, wsrc + (size_t)(c + 3) * 12288, tid);
        else CP_COMMIT();

        #pragma unroll
        for (int j = 0; j < 8; j++) {
            int col = c * 64 + j * 8 + cb;
            float2 bb = *(const float2*)&b1[col];
            float2 o0, o1;
            o0.x = acc[j][0] + bb.x; o0.y = acc[j][1] + bb.y;
            o1.x = acc[j][2] + bb.x; o1.y = acc[j][3] + bb.y;
            *(float2*)&g_G[(size_t)rbase * 384 + col]       = o0;
            *(float2*)&g_G[(size_t)(rbase + 8) * 384 + col] = o1;
        }
    }
}

// ---------------- kernel 3: main MLP (L3 replaced by mean-commuted GEMM) ----
__global__ __launch_bounds__(512, 1)
void mlp_kernel(const int* __restrict__ edges,
                const float* __restrict__ b2,
                const float* __restrict__ b3,
                float* __restrict__ out)
{
    extern __shared__ char smem[];
    const uint32_t sB  = smem_u32(smem);
    const uint32_t h1a = sB + H1OFF;

    const int tid  = threadIdx.x;
    const int wid  = tid >> 5;
    const int lane = tid & 31;
    const int rg   = wid >> 1;
    const int ch   = wid & 1;

    // ---- L1 A-fragments (src half) from global ----
    const int e0    = blockIdx.x * 128;
    const int rbase = rg * 16 + (lane >> 2);
    const int cb    = (lane & 3) * 2;
    const int src0 = edges[(size_t)(e0 + rbase) * 2 + 1];
    const int src1 = edges[(size_t)(e0 + rbase + 8) * 2 + 1];
    const __half* xs0 = g_X + (size_t)src0 * HIDDEN;
    const __half* xs1 = g_X + (size_t)src1 * HIDDEN;

    uint32_t A[48];
    #pragma unroll
    for (int kt = 0; kt < 12; kt++) {
        int c = kt * 16 + cb;
        A[kt * 4 + 0] = *(const uint32_t*)(xs0 + c);
        A[kt * 4 + 1] = *(const uint32_t*)(xs1 + c);
        A[kt * 4 + 2] = *(const uint32_t*)(xs0 + c + 8);
        A[kt * 4 + 3] = *(const uint32_t*)(xs1 + c + 8);
    }

    issue_chunk512(0, sB, tid);
    issue_chunk512(1, sB, tid);
    issue_chunk512(2, sB, tid);

    // zero-pad rows 8..15 of h2m (A-tile padding for the final GEMM)
    for (int i = tid; i < 800; i += 512)
        *(uint32_t*)(smem + H2MOFF + 3200 + i * 4) = 0;

    const uint32_t bo1 = (uint32_t)(lane & 15) * 144 + (uint32_t)(lane >> 4) * 16;
    const uint32_t bo2 = (uint32_t)(lane & 15) * 400 + (uint32_t)(lane >> 4) * 16;
    const int seg = blockIdx.x * 8 + rg;
    const float* gp = g_G + (size_t)seg * 384;

    const int r0 = rbase;
    const int r1 = rbase + 8;

    // ================= layer 1: K=192 (src), acc init = G; h1 -> smem ======
    #pragma unroll
    for (int c = 0; c < 6; c++) {
        CP_WAIT2();
        __syncthreads();
        float acc[4][4];
        #pragma unroll
        for (int j2 = 0; j2 < 4; j2++) {
            float2 gv = *(const float2*)(gp + c * 64 + ch * 32 + j2 * 8 + cb);
            acc[j2][0] = gv.x; acc[j2][1] = gv.y;
            acc[j2][2] = gv.x; acc[j2][3] = gv.y;
        }
        const uint32_t bufB = sB + (uint32_t)(c & 3) * SLOT + bo1;
        #pragma unroll
        for (int kc = 0; kc < 12; kc++) {
            #pragma unroll
            for (int lt = 0; lt < 2; lt++) {
                uint32_t b[4];
                ldsm4t(b, bufB + kc * 2304 + (ch * 2 + lt) * 32);
                mma16816(acc[2 * lt],     &A[kc * 4], b[0], b[1]);
                mma16816(acc[2 * lt + 1], &A[kc * 4], b[2], b[3]);
            }
        }
        issue_chunk512(c + 3, sB, tid);

        #pragma unroll
        for (int j2 = 0; j2 < 4; j2++) {
            int col = c * 64 + ch * 32 + j2 * 8 + cb;
            *(uint32_t*)(smem + H1OFF + (r0 * 392 + col) * 2) =
                packh2(gelu_exact(acc[j2][0]), gelu_exact(acc[j2][1]));
            *(uint32_t*)(smem + H1OFF + (r1 * 392 + col) * 2) =
                packh2(gelu_exact(acc[j2][2]), gelu_exact(acc[j2][3]));
        }
    }

    // ---- re-map warps for L2: (4 rg2 x 4 ch2) ----
    const int rg2 = wid >> 2;
    const int ch2 = wid & 3;
    const uint32_t aB1 = h1a + (((uint32_t)(rg2 * 32 + (lane & 15))) * 392 + (uint32_t)(lane >> 4) * 8) * 2;

    // ================= layer 2: K=384 from h1 smem =================
    float acc2[2][6][4];
    #pragma unroll
    for (int m = 0; m < 2; m++)
        #pragma unroll
        for (int n = 0; n < 6; n++)
            #pragma unroll
            for (int r = 0; r < 4; r++) acc2[m][n][r] = 0.0f;

    #pragma unroll
    for (int cc = 0; cc < 6; cc++) {
        CP_WAIT2();
        __syncthreads();
        const uint32_t bufB = sB + (uint32_t)((6 + cc) & 3) * SLOT + bo2;
        #pragma unroll
        for (int kl = 0; kl < 4; kl++) {
            uint32_t a0[4], a1[4];
            ldsm4(a0, aB1 + (uint32_t)(cc * 64 + kl * 16) * 2);
            ldsm4(a1, aB1 + (uint32_t)(16 * 392 + cc * 64 + kl * 16) * 2);
            #pragma unroll
            for (int lt = 0; lt < 3; lt++) {
                uint32_t b[4];
                ldsm4t(b, bufB + kl * 6400 + (ch2 * 3 + lt) * 32);
                mma16816(acc2[0][2 * lt],     a0, b[0], b[1]);
                mma16816(acc2[0][2 * lt + 1], a0, b[2], b[3]);
                mma16816(acc2[1][2 * lt],     a1, b[0], b[1]);
                mma16816(acc2[1][2 * lt + 1], a1, b[2], b[3]);
            }
        }
        issue_chunk512(9 + cc, sB, tid);   // ids 12-14 stream W3 pieces
    }

    // ---- L2 epilogue: gelu + in-register 16-row segment mean -> h2m fp16 ----
    #pragma unroll
    for (int m = 0; m < 2; m++) {
        int segl = rg2 * 2 + m;
        #pragma unroll
        for (int n = 0; n < 6; n++) {
            int col = ch2 * 48 + n * 8 + cb;
            float2 bb = *(const float2*)&b2[col];
            float s0 = gelu_exact(acc2[m][n][0] + bb.x) + gelu_exact(acc2[m][n][2] + bb.x);
            float s1 = gelu_exact(acc2[m][n][1] + bb.y) + gelu_exact(acc2[m][n][3] + bb.y);
            s0 += __shfl_xor_sync(0xFFFFFFFFu, s0, 4);
            s0 += __shfl_xor_sync(0xFFFFFFFFu, s0, 8);
            s0 += __shfl_xor_sync(0xFFFFFFFFu, s0, 16);
            s1 += __shfl_xor_sync(0xFFFFFFFFu, s1, 4);
            s1 += __shfl_xor_sync(0xFFFFFFFFu, s1, 8);
            s1 += __shfl_xor_sync(0xFFFFFFFFu, s1, 16);
            if (lane < 4)
                *(uint32_t*)(smem + H2MOFF + (segl * 200 + col) * 2) =
                    packh2(s0 * 0.0625f, s1 * 0.0625f);
        }
    }
    CP_WAIT0();
    __syncthreads();

    // ---- final: out[8 x 192] = h2m[8 x 192] @ W3 + b3 (12 warps) ----
    if (wid < 12) {
        float accF[2][4];
        #pragma unroll
        for (int t = 0; t < 2; t++)
            #pragma unroll
            for (int r = 0; r < 4; r++) accF[t][r] = 0.0f;

        const uint32_t aF = sB + H2MOFF + ((uint32_t)(lane & 15) * 200 + (uint32_t)(lane >> 4) * 8) * 2;
        #pragma unroll
        for (int kl = 0; kl < 12; kl++) {
            uint32_t a[4];
            ldsm4(a, aF + (uint32_t)(kl * 16) * 2);
            int p = kl >> 2, kr = (kl & 3) * 16;
            uint32_t b[4];
            ldsm4t(b, sB + (uint32_t)p * SLOT + (uint32_t)(kr + (lane & 15)) * 400
                      + (uint32_t)(lane >> 4) * 16 + (uint32_t)wid * 32);
            mma16816(accF[0], a, b[0], b[1]);
            mma16816(accF[1], a, b[2], b[3]);
        }
        int row = lane >> 2;   // segment 0..7
        #pragma unroll
        for (int t = 0; t < 2; t++) {
            int col = wid * 16 + t * 8 + cb;
            float2 bb = *(const float2*)&b3[col];
            float2 o;
            o.x = accF[t][0] + bb.x;
            o.y = accF[t][1] + bb.y;
            *(float2*)(out + (size_t)blockIdx.x * 1536 + row * 192 + col) = o;
        }
    }
}

// ---------------- launch ----------------
extern "C" void kernel_launch(void* const* d_in, const int* in_sizes, int n_in,
                              void* d_out, int out_size) {
    const float* mesh_pos   = (const float*)d_in[0];
    const int*   mesh_edges = (const int*)d_in[1];
    const float* W1 = (const float*)d_in[3];
    const float* b1 = (const float*)d_in[4];
    const float* W2 = (const float*)d_in[5];
    const float* b2 = (const float*)d_in[6];
    const float* W3 = (const float*)d_in[7];
    const float* b3 = (const float*)d_in[8];
    float* out = (float*)d_out;

    cudaFuncSetAttribute(gpart_kernel, cudaFuncAttributeMaxDynamicSharedMemorySize, SMEM_G);
    cudaFuncSetAttribute(mlp_kernel,   cudaFuncAttributeMaxDynamicSharedMemorySize, SMEM_MLP);

    prep_kernel<<<EMB_BLOCKS + WPR_BLOCKS, 256>>>(mesh_pos, W1, W2, W3);
    gpart_kernel<<<NSEG / 128, 256, SMEM_G>>>(b1);
    mlp_kernel<<<2048, 512, SMEM_MLP>>>(mesh_edges, b2, b3, out);
}

// round 16
// speedup vs baseline: 3.1471x; 1.0332x over previous
#include <cuda_runtime.h>
#include <cuda_fp16.h>
#include <cstdint>

#define HIDDEN 192
#define NNODES 262144
#define NSEG   16384

// ---------------- device scratch (no allocs allowed) ----------------
__device__ __half g_X[(size_t)NNODES * HIDDEN];     // node embeddings fp16
__device__ __align__(16) __half g_Wprep[258048];    // chunked weights
__device__ float g_G[(size_t)NSEG * 384];           // per-segment dst partial (+b1)

// ---------------- helpers ----------------
__device__ __forceinline__ uint32_t smem_u32(const void* p) {
    uint32_t a;
    asm("{ .reg .u64 t; cvta.to.shared.u64 t, %1; cvt.u32.u64 %0, t; }" : "=r"(a) : "l"(p));
    return a;
}
__device__ __forceinline__ void cp16(uint32_t dst, const __half* src) {
    unsigned long long g = __cvta_generic_to_global(src);
    asm volatile("cp.async.cg.shared.global [%0], [%1], 16;" :: "r"(dst), "l"(g) : "memory");
}
#define CP_COMMIT() asm volatile("cp.async.commit_group;" ::: "memory")
#define CP_WAIT2()  asm volatile("cp.async.wait_group 2;" ::: "memory")
#define CP_WAIT1()  asm volatile("cp.async.wait_group 1;" ::: "memory")
#define CP_WAIT0()  asm volatile("cp.async.wait_group 0;" ::: "memory")

__device__ __forceinline__ void ldsm4(uint32_t* r, uint32_t addr) {
    asm volatile("ldmatrix.sync.aligned.m8n8.x4.shared.b16 {%0,%1,%2,%3}, [%4];"
        : "=r"(r[0]), "=r"(r[1]), "=r"(r[2]), "=r"(r[3]) : "r"(addr));
}
__device__ __forceinline__ void ldsm4t(uint32_t* r, uint32_t addr) {
    asm volatile("ldmatrix.sync.aligned.m8n8.x4.trans.shared.b16 {%0,%1,%2,%3}, [%4];"
        : "=r"(r[0]), "=r"(r[1]), "=r"(r[2]), "=r"(r[3]) : "r"(addr));
}
__device__ __forceinline__ void mma16816(float* d, const uint32_t* a, uint32_t b0, uint32_t b1) {
    asm volatile("mma.sync.aligned.m16n8k16.row.col.f32.f16.f16.f32 "
        "{%0,%1,%2,%3}, {%4,%5,%6,%7}, {%8,%9}, {%0,%1,%2,%3};"
        : "+f"(d[0]), "+f"(d[1]), "+f"(d[2]), "+f"(d[3])
        : "r"(a[0]), "r"(a[1]), "r"(a[2]), "r"(a[3]), "r"(b0), "r"(b1));
}
__device__ __forceinline__ float gelu_exact(float x) {
    return 0.5f * x * (1.0f + erff(x * 0.70710678118654752f));
}
__device__ __forceinline__ uint32_t packh2(float x, float y) {
    __half2 h = __floats2half2_rn(x, y);
    return *reinterpret_cast<uint32_t*>(&h);
}

// ---------------- kernel 1: fused embed + weight prep ----------------
#define EMB_BLOCKS 24576
#define WPR_BLOCKS 1008
__global__ void prep_kernel(const float* __restrict__ pos,
                            const float* __restrict__ W1,
                            const float* __restrict__ W2,
                            const float* __restrict__ W3) {
    int b = blockIdx.x;
    if (b < EMB_BLOCKS) {
        int idx = b * 256 + threadIdx.x;
        int n = idx / 24;
        int t = idx - n * 24;
        int d = t >> 3, q = t & 7;
        int j0 = q * 4;
        float p = pos[n * 3 + d];
        float s[4], c[4];
        #pragma unroll
        for (int i = 0; i < 4; i++) {
            float omega = exp2f(-(float)(j0 + i) * (13.287712379549449f / 32.0f));
            __sincosf(p * omega, &s[i], &c[i]);
        }
        uint2 sv, cv;
        sv.x = packh2(s[0], s[1]); sv.y = packh2(s[2], s[3]);
        cv.x = packh2(c[0], c[1]); cv.y = packh2(c[2], c[3]);
        __half* xp = g_X + (size_t)n * HIDDEN + d * 64;
        *(uint2*)(xp + j0)      = sv;
        *(uint2*)(xp + 32 + j0) = cv;
    } else {
        int e = (b - EMB_BLOCKS) * 256 + threadIdx.x;
        if (e >= 258048) return;
        float w;
        if (e < 73728) {
            int p = e / 12288, r = e - p * 12288;
            int k = r >> 6, n = r & 63;
            w = W1[k * 384 + p * 64 + n];
        } else if (e < 147456) {
            int f = e - 73728;
            int p = f / 12288, r = f - p * 12288;
            int k = r >> 6, n = r & 63;
            w = W1[(192 + k) * 384 + p * 64 + n];
        } else if (e < 221184) {
            int f = e - 147456;
            int p = f / 12288, r = f - p * 12288;
            int k = r / 192, n = r - k * 192;
            w = W2[(p * 64 + k) * 192 + n];
        } else {
            int f = e - 221184;
            int p = f / 12288, r = f - p * 12288;
            int k = r / 192, n = r - k * 192;
            w = W3[(p * 64 + k) * 192 + n];
        }
        g_Wprep[e] = __float2half(w);
    }
}

#define SLOT 27648
#define SMEM_G (4 * SLOT)
// mlp smem: ring-2 + h1(64x392h) + h2m(16x200h)
#define H1OFF   (2 * SLOT)                // 55296
#define H2MOFF  (H1OFF + 50176)           // 105472
#define SMEM_MLP (H2MOFF + 6400)          // 111872  -> 2 CTAs/SM

__device__ __forceinline__ void issue_piece256(uint32_t dst, const __half* src, int tid) {
    #pragma unroll
    for (int i = 0; i < 6; i++) {
        int idx = tid + i * 256;
        int row = idx >> 3, q = idx & 7;
        cp16(dst + row * 144 + q * 16, src + idx * 8);
    }
    CP_COMMIT();
}
// mlp loader (256 threads, ring-2)
__device__ __forceinline__ void issue_chunk256(int id, uint32_t sB, int tid) {
    uint32_t dst = sB + (uint32_t)(id & 1) * SLOT;
    if (id < 6) {
        const __half* src = g_Wprep + (size_t)id * 12288;
        #pragma unroll
        for (int i = 0; i < 6; i++) {
            int idx = tid + i * 256;
            int row = idx >> 3, q = idx & 7;
            cp16(dst + row * 144 + q * 16, src + idx * 8);
        }
    } else {
        const __half* src = g_Wprep + 147456 + (size_t)(id - 6) * 12288;
        #pragma unroll
        for (int i = 0; i < 6; i++) {
            int idx = tid + i * 256;
            int row = idx / 24, q = idx - row * 24;
            cp16(dst + row * 400 + q * 16, src + idx * 8);
        }
    }
    CP_COMMIT();
}

// ---------------- kernel 2: per-segment dst partial G ------------------------
__global__ __launch_bounds__(256, 1)
void gpart_kernel(const float* __restrict__ b1) {
    extern __shared__ char smem[];
    const uint32_t sB = smem_u32(smem);
    const int tid  = threadIdx.x;
    const int wid  = tid >> 5;
    const int lane = tid & 31;

    const int rbase = blockIdx.x * 128 + wid * 16 + (lane >> 2);
    const int cb    = (lane & 3) * 2;
    const __half* x0 = g_X + (size_t)rbase * HIDDEN;
    const __half* x1 = g_X + (size_t)(rbase + 8) * HIDDEN;

    uint32_t A[48];
    #pragma unroll
    for (int kt = 0; kt < 12; kt++) {
        int c = kt * 16 + cb;
        A[kt * 4 + 0] = *(const uint32_t*)(x0 + c);
        A[kt * 4 + 1] = *(const uint32_t*)(x1 + c);
        A[kt * 4 + 2] = *(const uint32_t*)(x0 + c + 8);
        A[kt * 4 + 3] = *(const uint32_t*)(x1 + c + 8);
    }

    const __half* wsrc = g_Wprep + 73728;
    issue_piece256(sB + 0 * SLOT, wsrc + 0 * 12288, tid);
    issue_piece256(sB + 1 * SLOT, wsrc + 1 * 12288, tid);
    issue_piece256(sB + 2 * SLOT, wsrc + 2 * 12288, tid);

    const uint32_t bo1 = (uint32_t)(lane & 15) * 144 + (uint32_t)(lane >> 4) * 16;

    #pragma unroll
    for (int c = 0; c < 6; c++) {
        CP_WAIT2();
        __syncthreads();
        float acc[8][4];
        #pragma unroll
        for (int j = 0; j < 8; j++)
            #pragma unroll
            for (int r = 0; r < 4; r++) acc[j][r] = 0.0f;

        const uint32_t bufB = sB + (uint32_t)(c & 3) * SLOT + bo1;
        #pragma unroll
        for (int kc = 0; kc < 12; kc++) {
            #pragma unroll
            for (int nt = 0; nt < 4; nt++) {
                uint32_t b[4];
                ldsm4t(b, bufB + kc * 2304 + nt * 32);
                mma16816(acc[2 * nt],     &A[kc * 4], b[0], b[1]);
                mma16816(acc[2 * nt + 1], &A[kc * 4], b[2], b[3]);
            }
        }
        if (c + 3 < 6) issue_piece256(sB + (uint32_t)((c + 3) & 3) * SLOT, wsrc + (size_t)(c + 3) * 12288, tid);
        else CP_COMMIT();

        #pragma unroll
        for (int j = 0; j < 8; j++) {
            int col = c * 64 + j * 8 + cb;
            float2 bb = *(const float2*)&b1[col];
            float2 o0, o1;
            o0.x = acc[j][0] + bb.x; o0.y = acc[j][1] + bb.y;
            o1.x = acc[j][2] + bb.x; o1.y = acc[j][3] + bb.y;
            *(float2*)&g_G[(size_t)rbase * 384 + col]       = o0;
            *(float2*)&g_G[(size_t)(rbase + 8) * 384 + col] = o1;
        }
    }
}

// ---------------- kernel 3: main MLP, 64 rows/CTA, 2 CTAs/SM ----------------
__global__ __launch_bounds__(256, 2)
void mlp_kernel(const int* __restrict__ edges,
                const float* __restrict__ b2,
                const float* __restrict__ b3,
                float* __restrict__ out)
{
    extern __shared__ char smem[];
    const uint32_t sB  = smem_u32(smem);
    const uint32_t h1a = sB + H1OFF;

    const int tid  = threadIdx.x;
    const int wid  = tid >> 5;
    const int lane = tid & 31;
    const int rg   = wid >> 1;        // 0..3 (16-row group = one segment)
    const int ch   = wid & 1;

    // ---- L1 A-fragments (src half) from global ----
    const int e0    = blockIdx.x * 64;
    const int rbase = rg * 16 + (lane >> 2);
    const int cb    = (lane & 3) * 2;
    const int src0 = edges[(size_t)(e0 + rbase) * 2 + 1];
    const int src1 = edges[(size_t)(e0 + rbase + 8) * 2 + 1];
    const __half* xs0 = g_X + (size_t)src0 * HIDDEN;
    const __half* xs1 = g_X + (size_t)src1 * HIDDEN;

    uint32_t A[48];
    #pragma unroll
    for (int kt = 0; kt < 12; kt++) {
        int c = kt * 16 + cb;
        A[kt * 4 + 0] = *(const uint32_t*)(xs0 + c);
        A[kt * 4 + 1] = *(const uint32_t*)(xs1 + c);
        A[kt * 4 + 2] = *(const uint32_t*)(xs0 + c + 8);
        A[kt * 4 + 3] = *(const uint32_t*)(xs1 + c + 8);
    }

    issue_chunk256(0, sB, tid);
    issue_chunk256(1, sB, tid);

    // zero-pad h2m rows 4..15
    for (int i = tid; i < 1200; i += 256)
        *(uint32_t*)(smem + H2MOFF + 1600 + i * 4) = 0;

    const uint32_t bo1 = (uint32_t)(lane & 15) * 144 + (uint32_t)(lane >> 4) * 16;
    const uint32_t bo2 = (uint32_t)(lane & 15) * 400 + (uint32_t)(lane >> 4) * 16;
    const int seg = blockIdx.x * 4 + rg;
    const float* gp = g_G + (size_t)seg * 384;

    const int r0 = rbase;
    const int r1 = rbase + 8;

    // ================= layer 1: K=192 (src), acc init = G; h1 -> smem ======
    #pragma unroll
    for (int c = 0; c < 6; c++) {
        CP_WAIT1();
        __syncthreads();
        float acc[4][4];
        #pragma unroll
        for (int j2 = 0; j2 < 4; j2++) {
            float2 gv = *(const float2*)(gp + c * 64 + ch * 32 + j2 * 8 + cb);
            acc[j2][0] = gv.x; acc[j2][1] = gv.y;
            acc[j2][2] = gv.x; acc[j2][3] = gv.y;
        }
        const uint32_t bufB = sB + (uint32_t)(c & 1) * SLOT + bo1;
        #pragma unroll
        for (int kc = 0; kc < 12; kc++) {
            #pragma unroll
            for (int lt = 0; lt < 2; lt++) {
                uint32_t b[4];
                ldsm4t(b, bufB + kc * 2304 + (ch * 2 + lt) * 32);
                mma16816(acc[2 * lt],     &A[kc * 4], b[0], b[1]);
                mma16816(acc[2 * lt + 1], &A[kc * 4], b[2], b[3]);
            }
        }
        __syncthreads();                 // all reads of slot (c&1) complete
        issue_chunk256(c + 2, sB, tid);  // safe to overwrite

        #pragma unroll
        for (int j2 = 0; j2 < 4; j2++) {
            int col = c * 64 + ch * 32 + j2 * 8 + cb;
            *(uint32_t*)(smem + H1OFF + (r0 * 392 + col) * 2) =
                packh2(gelu_exact(acc[j2][0]), gelu_exact(acc[j2][1]));
            *(uint32_t*)(smem + H1OFF + (r1 * 392 + col) * 2) =
                packh2(gelu_exact(acc[j2][2]), gelu_exact(acc[j2][3]));
        }
    }

    // ---- re-map warps for L2: (2 rg2 x 4 ch2) ----
    const int rg2 = wid >> 2;          // 0..1, rows rg2*32..+31
    const int ch2 = wid & 3;           // cols ch2*48..+47
    const uint32_t aB1 = h1a + (((uint32_t)(rg2 * 32 + (lane & 15))) * 392 + (uint32_t)(lane >> 4) * 8) * 2;

    // ================= layer 2: K=384 from h1 smem =================
    float acc2[2][6][4];
    #pragma unroll
    for (int m = 0; m < 2; m++)
        #pragma unroll
        for (int n = 0; n < 6; n++)
            #pragma unroll
            for (int r = 0; r < 4; r++) acc2[m][n][r] = 0.0f;

    #pragma unroll
    for (int cc = 0; cc < 6; cc++) {
        CP_WAIT1();
        __syncthreads();
        const uint32_t bufB = sB + (uint32_t)((6 + cc) & 1) * SLOT + bo2;
        #pragma unroll
        for (int kl = 0; kl < 4; kl++) {
            uint32_t a0[4], a1[4];
            ldsm4(a0, aB1 + (uint32_t)(cc * 64 + kl * 16) * 2);
            ldsm4(a1, aB1 + (uint32_t)(16 * 392 + cc * 64 + kl * 16) * 2);
            #pragma unroll
            for (int lt = 0; lt < 3; lt++) {
                uint32_t b[4];
                ldsm4t(b, bufB + kl * 6400 + (ch2 * 3 + lt) * 32);
                mma16816(acc2[0][2 * lt],     a0, b[0], b[1]);
                mma16816(acc2[0][2 * lt + 1], a0, b[2], b[3]);
                mma16816(acc2[1][2 * lt],     a1, b[0], b[1]);
                mma16816(acc2[1][2 * lt + 1], a1, b[2], b[3]);
            }
        }
        __syncthreads();
        issue_chunk256(8 + cc, sB, tid);   // 8..13 (12,13 = W3 pieces 0,1)
    }

    // ---- L2 epilogue: gelu + 16-row segment mean -> h2m fp16 ----
    #pragma unroll
    for (int m = 0; m < 2; m++) {
        int segl = rg2 * 2 + m;            // 0..3
        #pragma unroll
        for (int n = 0; n < 6; n++) {
            int col = ch2 * 48 + n * 8 + cb;
            float2 bb = *(const float2*)&b2[col];
            float s0 = gelu_exact(acc2[m][n][0] + bb.x) + gelu_exact(acc2[m][n][2] + bb.x);
            float s1 = gelu_exact(acc2[m][n][1] + bb.y) + gelu_exact(acc2[m][n][3] + bb.y);
            s0 += __shfl_xor_sync(0xFFFFFFFFu, s0, 4);
            s0 += __shfl_xor_sync(0xFFFFFFFFu, s0, 8);
            s0 += __shfl_xor_sync(0xFFFFFFFFu, s0, 16);
            s1 += __shfl_xor_sync(0xFFFFFFFFu, s1, 4);
            s1 += __shfl_xor_sync(0xFFFFFFFFu, s1, 8);
            s1 += __shfl_xor_sync(0xFFFFFFFFu, s1, 16);
            if (lane < 4)
                *(uint32_t*)(smem + H2MOFF + (segl * 200 + col) * 2) =
                    packh2(s0 * 0.0625f, s1 * 0.0625f);
        }
    }

    // ---- final: out[4 x 192] = h2m[4(+pad) x 192] @ W3 + b3 ----
    float accF[4][4];
    #pragma unroll
    for (int t = 0; t < 4; t++)
        #pragma unroll
        for (int r = 0; r < 4; r++) accF[t][r] = 0.0f;

    const uint32_t aF = sB + H2MOFF + ((uint32_t)(lane & 15) * 200 + (uint32_t)(lane >> 4) * 8) * 2;
    #pragma unroll
    for (int p = 0; p < 3; p++) {
        if (p < 2) { CP_WAIT1(); } else { CP_WAIT0(); }
        __syncthreads();                   // piece 12+p resident; h2m visible (p==0)
        if (wid < 6) {
            const uint32_t bslot = sB + (uint32_t)((12 + p) & 1) * SLOT;
            #pragma unroll
            for (int klp = 0; klp < 4; klp++) {
                uint32_t a[4];
                ldsm4(a, aF + (uint32_t)((p * 4 + klp) * 16) * 2);
                #pragma unroll
                for (int hh = 0; hh < 2; hh++) {
                    uint32_t b[4];
                    ldsm4t(b, bslot + (uint32_t)(klp * 16 + (lane & 15)) * 400
                              + (uint32_t)(lane >> 4) * 16 + (uint32_t)wid * 64 + hh * 32);
                    mma16816(accF[2 * hh],     a, b[0], b[1]);
                    mma16816(accF[2 * hh + 1], a, b[2], b[3]);
                }
            }
        }
        if (p == 0) {
            __syncthreads();               // piece 12 reads done
            issue_chunk256(14, sB, tid);   // piece 2 -> slot 0
        }
    }

    {
        int row = lane >> 2;               // 0..7; rows 0..3 are real segments
        if (wid < 6 && row < 4) {
            #pragma unroll
            for (int t = 0; t < 4; t++) {
                int col = wid * 32 + t * 8 + cb;
                float2 bb = *(const float2*)&b3[col];
                float2 o;
                o.x = accF[t][0] + bb.x;
                o.y = accF[t][1] + bb.y;
                *(float2*)(out + (size_t)blockIdx.x * 768 + row * 192 + col) = o;
            }
        }
    }
}

// ---------------- launch ----------------
extern "C" void kernel_launch(void* const* d_in, const int* in_sizes, int n_in,
                              void* d_out, int out_size) {
    const float* mesh_pos   = (const float*)d_in[0];
    const int*   mesh_edges = (const int*)d_in[1];
    const float* W1 = (const float*)d_in[3];
    const float* b1 = (const float*)d_in[4];
    const float* W2 = (const float*)d_in[5];
    const float* b2 = (const float*)d_in[6];
    const float* W3 = (const float*)d_in[7];
    const float* b3 = (const float*)d_in[8];
    float* out = (float*)d_out;

    cudaFuncSetAttribute(gpart_kernel, cudaFuncAttributeMaxDynamicSharedMemorySize, SMEM_G);
    cudaFuncSetAttribute(mlp_kernel,   cudaFuncAttributeMaxDynamicSharedMemorySize, SMEM_MLP);

    prep_kernel<<<EMB_BLOCKS + WPR_BLOCKS, 256>>>(mesh_pos, W1, W2, W3);
    gpart_kernel<<<NSEG / 128, 256, SMEM_G>>>(b1);
    mlp_kernel<<<4096, 256, SMEM_MLP>>>(mesh_edges, b2, b3, out);
}